// round 4
// baseline (speedup 1.0000x reference)
#include <cuda_runtime.h>
#include <cuda_bf16.h>
#include <cstdint>

// Problem constants
#define BB   4
#define TT   1024
#define EE   512
#define SSQ  1536   // S = T + E
#define HHC  1024   // hidden
#define NHH  16
#define HDD  64
#define LN_EPS 1e-5f
#define SCALING 0.125f   // sqrt(64)/64

// -log2(10000)/32
#define NLOG2F_STEP (-0.4152410118609203f)

// ---------------- scratch ----------------
__device__ float g_Q  [BB*TT*HHC];    // rope'd Q, [B,T,H]
__device__ float g_K  [BB*TT*HHC];    // raw K projection
__device__ float g_V  [BB*TT*HHC];    // raw V projection
__device__ float g_att[BB*TT*HHC];    // attention out pre-LN
__device__ float g_ln [BB*TT*HHC];    // LN output
// bf16 hi/lo split K (gathered+rope'd), [B,S,H]
__device__ __nv_bfloat16 g_Khi[BB*SSQ*HHC];
__device__ __nv_bfloat16 g_Klo[BB*SSQ*HHC];
// bf16 hi/lo split V, transposed per head: [B*NH, HD, S]
__device__ __nv_bfloat16 g_Vthi[BB*NHH*HDD*SSQ];
__device__ __nv_bfloat16 g_Vtlo[BB*NHH*HDD*SSQ];

// ---------------- helpers ----------------
__device__ __forceinline__ uint32_t f2tf(float f) {
    uint32_t u; asm("cvt.rna.tf32.f32 %0, %1;" : "=r"(u) : "f"(f)); return u;
}

__device__ __forceinline__ void bsplit(float x, __nv_bfloat16& h, __nv_bfloat16& l) {
    h = __float2bfloat16_rn(x);
    l = __float2bfloat16_rn(x - __bfloat162float(h));
}

__device__ __forceinline__ void mma16816(float* c,
    uint32_t a0, uint32_t a1, uint32_t a2, uint32_t a3,
    uint32_t b0, uint32_t b1)
{
    asm volatile(
        "mma.sync.aligned.m16n8k16.row.col.f32.bf16.bf16.f32 "
        "{%0,%1,%2,%3},{%4,%5,%6,%7},{%8,%9},{%0,%1,%2,%3};"
        : "+f"(c[0]), "+f"(c[1]), "+f"(c[2]), "+f"(c[3])
        : "r"(a0), "r"(a1), "r"(a2), "r"(a3), "r"(b0), "r"(b1));
}

__device__ __forceinline__ void ldsm4(uint32_t addr,
    uint32_t& r0, uint32_t& r1, uint32_t& r2, uint32_t& r3)
{
    asm volatile("ldmatrix.sync.aligned.m8n8.x4.shared.b16 {%0,%1,%2,%3}, [%4];"
        : "=r"(r0), "=r"(r1), "=r"(r2), "=r"(r3) : "r"(addr));
}

__device__ __forceinline__ void cpa16(uint32_t daddr, const void* src) {
    asm volatile("cp.async.cg.shared.global [%0], [%1], 16;" :: "r"(daddr), "l"(src));
}
#define CP_COMMIT asm volatile("cp.async.commit_group;")
#define CP_WAIT1  asm volatile("cp.async.wait_group 1;")
#define CP_WAIT0  asm volatile("cp.async.wait_group 0;")

// ---------------- GEMM: C[M,N] = alpha * A[M,K] * B[N,K]^T (tf32 mma.sync) ----------------
__global__ __launch_bounds__(256) void gemm_tf32_nt(
    const float* __restrict__ A, const float* __restrict__ Bm,
    float* __restrict__ C, int M, int N, int K, float alpha)
{
    __shared__ uint32_t As[128 * 36];
    __shared__ uint32_t Bs[128 * 36];

    const int tid  = threadIdx.x;
    const int lane = tid & 31;
    const int wid  = tid >> 5;
    const int gid  = lane >> 2;
    const int tig  = lane & 3;
    const int wm   = (wid & 1) * 64;
    const int wn   = (wid >> 1) * 32;
    const int bm   = blockIdx.y * 128;
    const int bn   = blockIdx.x * 128;

    float acc[4][4][4];
#pragma unroll
    for (int i = 0; i < 4; i++)
#pragma unroll
        for (int j = 0; j < 4; j++)
#pragma unroll
            for (int r = 0; r < 4; r++) acc[i][j][r] = 0.f;

    for (int kt = 0; kt < K; kt += 32) {
#pragma unroll
        for (int it = 0; it < 4; it++) {
            int f4 = tid + it * 256;
            int r  = f4 >> 3;
            int c  = (f4 & 7) << 2;
            float4 a = *reinterpret_cast<const float4*>(A + (size_t)(bm + r) * K + kt + c);
            uint32_t* d = &As[r * 36 + c];
            d[0] = f2tf(a.x); d[1] = f2tf(a.y); d[2] = f2tf(a.z); d[3] = f2tf(a.w);
            float4 b = *reinterpret_cast<const float4*>(Bm + (size_t)(bn + r) * K + kt + c);
            uint32_t* e = &Bs[r * 36 + c];
            e[0] = f2tf(b.x); e[1] = f2tf(b.y); e[2] = f2tf(b.z); e[3] = f2tf(b.w);
        }
        __syncthreads();
#pragma unroll
        for (int ks = 0; ks < 32; ks += 8) {
            uint32_t af[4][4], bf[4][2];
#pragma unroll
            for (int mt = 0; mt < 4; mt++) {
                const uint32_t* p = &As[(wm + mt * 16 + gid) * 36 + ks + tig];
                af[mt][0] = p[0];
                af[mt][1] = p[8 * 36];
                af[mt][2] = p[4];
                af[mt][3] = p[8 * 36 + 4];
            }
#pragma unroll
            for (int nt = 0; nt < 4; nt++) {
                const uint32_t* p = &Bs[(wn + nt * 8 + gid) * 36 + ks + tig];
                bf[nt][0] = p[0];
                bf[nt][1] = p[4];
            }
#pragma unroll
            for (int mt = 0; mt < 4; mt++)
#pragma unroll
                for (int nt = 0; nt < 4; nt++)
                    asm volatile(
                        "mma.sync.aligned.m16n8k8.row.col.f32.tf32.tf32.f32 "
                        "{%0,%1,%2,%3},{%4,%5,%6,%7},{%8,%9},{%0,%1,%2,%3};"
                        : "+f"(acc[mt][nt][0]), "+f"(acc[mt][nt][1]),
                          "+f"(acc[mt][nt][2]), "+f"(acc[mt][nt][3])
                        : "r"(af[mt][0]), "r"(af[mt][1]), "r"(af[mt][2]), "r"(af[mt][3]),
                          "r"(bf[nt][0]), "r"(bf[nt][1]));
        }
        __syncthreads();
    }

#pragma unroll
    for (int mt = 0; mt < 4; mt++) {
#pragma unroll
        for (int nt = 0; nt < 4; nt++) {
            int r0 = bm + wm + mt * 16 + gid;
            int c0 = bn + wn + nt * 8 + tig * 2;
            float2 v01 = make_float2(acc[mt][nt][0] * alpha, acc[mt][nt][1] * alpha);
            float2 v23 = make_float2(acc[mt][nt][2] * alpha, acc[mt][nt][3] * alpha);
            *reinterpret_cast<float2*>(C + (size_t)r0 * N + c0)       = v01;
            *reinterpret_cast<float2*>(C + (size_t)(r0 + 8) * N + c0) = v23;
        }
    }
}

// ---------------- RoPE on Q (in place), fp32 math ----------------
__global__ __launch_bounds__(256) void rope_q_kernel()
{
    int idx = blockIdx.x * blockDim.x + threadIdx.x;
    int i    = idx & 31;
    int head = (idx >> 5) & (NHH - 1);
    int row  = idx >> 9;
    int t    = row & (TT - 1);
    float* p = g_Q + (size_t)row * HHC + head * HDD + i;
    float x1 = p[0], x2 = p[32];
    float invf = exp2f(NLOG2F_STEP * (float)i);
    float arg = (float)t * invf;
    float s, c; sincosf(arg, &s, &c);
    p[0]  = x1 * c - x2 * s;
    p[32] = x2 * c + x1 * s;
}

// ---------------- Gather K + RoPE, write bf16 hi/lo [B,S,H] ----------------
__global__ __launch_bounds__(256) void gather_k_kernel(const int* __restrict__ outcell)
{
    int idx = blockIdx.x * blockDim.x + threadIdx.x;
    int i    = idx & 31;
    int head = (idx >> 5) & (NHH - 1);
    int rest = idx >> 9;
    int s    = rest % SSQ;
    int b    = rest / SSQ;
    int src  = (s < TT) ? s : outcell[b * EE + (s - TT)];

    size_t soff = (size_t)(b * TT + src) * HHC + head * HDD + i;
    size_t doff = (size_t)(b * SSQ + s) * HHC + head * HDD + i;

    float k1 = g_K[soff], k2 = g_K[soff + 32];
    float invf = exp2f(NLOG2F_STEP * (float)i);
    float arg = (float)s * invf;
    float sn, cs; sincosf(arg, &sn, &cs);
    float r1 = k1 * cs - k2 * sn;
    float r2 = k2 * cs + k1 * sn;
    __nv_bfloat16 hh, ll;
    bsplit(r1, hh, ll); g_Khi[doff]      = hh; g_Klo[doff]      = ll;
    bsplit(r2, hh, ll); g_Khi[doff + 32] = hh; g_Klo[doff + 32] = ll;
}

// ---------------- Gather V transposed, write bf16 hi/lo [B*NH, HD, S] ----------------
// grid = BB*NHH*HDD*6 blocks of 256 (s fastest for coalesced writes)
__global__ __launch_bounds__(256) void gather_vt_kernel(const int* __restrict__ outcell)
{
    int s    = (blockIdx.x % 6) * 256 + threadIdx.x;
    int rest = blockIdx.x / 6;          // bh*64 + d
    int d    = rest & (HDD - 1);
    int bh   = rest >> 6;
    int b    = bh >> 4, h = bh & (NHH - 1);
    int src  = (s < TT) ? s : outcell[b * EE + (s - TT)];

    float v = g_V[(size_t)(b * TT + src) * HHC + h * HDD + d];
    __nv_bfloat16 hh, ll;
    bsplit(v, hh, ll);
    size_t o = (size_t)rest * SSQ + s;
    g_Vthi[o] = hh;
    g_Vtlo[o] = ll;
}

// ---------------- Attention: flash, bf16x2-split mma, cp.async double-buffer ----------------
// SMEM bf16 layout (bytes):
//   Qhi  [128][72] @ 0       (18432)
//   Qlo  [128][72] @ 18432   (18432)
//   buf{0,1} @ 36864 + sel*36864, each:
//     Khi [64][72] +0, Klo +9216, Vthi +18432, Vtlo +27648   (9216 each)
//   maskS (64 floats) @ 110592
#define ATT_SMEM 110848
__global__ __launch_bounds__(256) void attn_mma_kernel(
    const float* __restrict__ bias, const float* __restrict__ lw,
    const unsigned char* __restrict__ keypad, const unsigned char* __restrict__ expand)
{
    extern __shared__ char smraw[];
    __nv_bfloat16* sb = (__nv_bfloat16*)smraw;
    float* maskS = (float*)(smraw + 110592);
    const uint32_t sbase = (uint32_t)__cvta_generic_to_shared(smraw);

    const int tid  = threadIdx.x;
    const int lane = tid & 31;
    const int w    = tid >> 5;
    const int gid  = lane >> 2;
    const int tig  = lane & 3;
    const int h = blockIdx.y, b = blockIdx.z;
    const int bh = b * NHH + h;
    const int q0 = blockIdx.x * 128;
    const int qw = w * 16;

    const __nv_bfloat16* gKhi  = g_Khi  + (size_t)b * SSQ * HHC + h * HDD;
    const __nv_bfloat16* gKlo  = g_Klo  + (size_t)b * SSQ * HHC + h * HDD;
    const __nv_bfloat16* gVthi = g_Vthi + (size_t)bh * HDD * SSQ;
    const __nv_bfloat16* gVtlo = g_Vtlo + (size_t)bh * HDD * SSQ;

    // ---- issue tile kc into buffer sel (all threads) ----
    auto issue_tile = [&](int kc, int sel) {
        uint32_t bbase = sbase + 36864u + (uint32_t)sel * 36864u;
#pragma unroll
        for (int half = 0; half < 2; half++) {
            int chunk = tid + half * 256;       // 0..511
            int row = chunk >> 3;               // 0..63
            int ce  = (chunk & 7) * 8;          // bf16 offset 0..56
            uint32_t so = (uint32_t)(row * 72 + ce) * 2;
            cpa16(bbase + so,          gKhi  + (size_t)(kc + row) * HHC + ce);
            cpa16(bbase + 9216u + so,  gKlo  + (size_t)(kc + row) * HHC + ce);
            cpa16(bbase + 18432u + so, gVthi + (size_t)row * SSQ + kc + ce);
            cpa16(bbase + 27648u + so, gVtlo + (size_t)row * SSQ + kc + ce);
        }
        CP_COMMIT;
    };

    issue_tile(0, 0);

    // ---- stage Q (split to bf16 hi/lo) ----
    __nv_bfloat16* Qhi = sb;
    __nv_bfloat16* Qlo = sb + 9216;
#pragma unroll
    for (int it = 0; it < 8; it++) {
        int f4 = tid + it * 256;
        int r  = f4 >> 4;
        int c  = (f4 & 15) * 4;
        float4 v = *(const float4*)(g_Q + (size_t)(b * TT + q0 + r) * HHC + h * HDD + c);
        __nv_bfloat16 hh, ll;
        bsplit(v.x, hh, ll); Qhi[r*72+c+0] = hh; Qlo[r*72+c+0] = ll;
        bsplit(v.y, hh, ll); Qhi[r*72+c+1] = hh; Qlo[r*72+c+1] = ll;
        bsplit(v.z, hh, ll); Qhi[r*72+c+2] = hh; Qlo[r*72+c+2] = ll;
        bsplit(v.w, hh, ll); Qhi[r*72+c+3] = hh; Qlo[r*72+c+3] = ll;
    }
    __syncthreads();

    // ---- Q fragments (resident) ----
    uint32_t qh[4][4], ql[4][4];
#pragma unroll
    for (int ks = 0; ks < 4; ks++) {
        int c0 = 2 * tig + 16 * ks;
        qh[ks][0] = *(uint32_t*)&Qhi[(qw + gid)     * 72 + c0];
        qh[ks][1] = *(uint32_t*)&Qhi[(qw + gid + 8) * 72 + c0];
        qh[ks][2] = *(uint32_t*)&Qhi[(qw + gid)     * 72 + c0 + 8];
        qh[ks][3] = *(uint32_t*)&Qhi[(qw + gid + 8) * 72 + c0 + 8];
        ql[ks][0] = *(uint32_t*)&Qlo[(qw + gid)     * 72 + c0];
        ql[ks][1] = *(uint32_t*)&Qlo[(qw + gid + 8) * 72 + c0];
        ql[ks][2] = *(uint32_t*)&Qlo[(qw + gid)     * 72 + c0 + 8];
        ql[ks][3] = *(uint32_t*)&Qlo[(qw + gid + 8) * 72 + c0 + 8];
    }

    float m0 = -INFINITY, m1 = -INFINITY, l0 = 0.f, l1 = 0.f;
    float pacc[8][4];
#pragma unroll
    for (int nt = 0; nt < 8; nt++)
#pragma unroll
        for (int c = 0; c < 4; c++) pacc[nt][c] = 0.f;

    const float* biasB = bias + ((size_t)(b * NHH + h) * TT + q0) * SSQ;
    const float* lwB   = lw   + ((size_t)b * TT + q0) * SSQ;

    // ldmatrix per-lane offset within a [rows][72] bf16 array (bytes)
    const uint32_t lanoff =
        (uint32_t)((((lane >> 4) & 1) * 8 + (lane & 7)) * 72 + ((lane >> 3) & 1) * 8) * 2;

    for (int i = 0; i < 24; i++) {
        const int kc = i * 64;
        const int cur = i & 1;
        if (i < 23) issue_tile(kc + 64, cur ^ 1);
        if (i < 23) { CP_WAIT1; } else { CP_WAIT0; }
        if (tid < 64) {
            int s = kc + tid;
            unsigned char mk = (s < TT) ? keypad[b * TT + s] : expand[b * EE + (s - TT)];
            maskS[tid] = mk ? 1.f : 0.f;
        }
        __syncthreads();

        const uint32_t kbHi = sbase + 36864u + (uint32_t)cur * 36864u;
        const uint32_t kbLo = kbHi + 9216u;
        const uint32_t vbHi = kbHi + 18432u;
        const uint32_t vbLo = kbHi + 27648u;

        // ---- QK^T (3-pass bf16x2, ldmatrix B-frags) ----
        float sacc[8][4];
#pragma unroll
        for (int nt = 0; nt < 8; nt++)
#pragma unroll
            for (int c = 0; c < 4; c++) sacc[nt][c] = 0.f;

#pragma unroll
        for (int ks = 0; ks < 4; ks++) {
#pragma unroll
            for (int p = 0; p < 4; p++) {
                uint32_t off = lanoff + (uint32_t)(p * 2304 + ks * 32);
                uint32_t bh0, bh1, bh2, bh3, bl0, bl1, bl2, bl3;
                ldsm4(kbHi + off, bh0, bh1, bh2, bh3);
                ldsm4(kbLo + off, bl0, bl1, bl2, bl3);
                mma16816(sacc[2*p],   qh[ks][0], qh[ks][1], qh[ks][2], qh[ks][3], bh0, bh1);
                mma16816(sacc[2*p],   ql[ks][0], ql[ks][1], ql[ks][2], ql[ks][3], bh0, bh1);
                mma16816(sacc[2*p],   qh[ks][0], qh[ks][1], qh[ks][2], qh[ks][3], bl0, bl1);
                mma16816(sacc[2*p+1], qh[ks][0], qh[ks][1], qh[ks][2], qh[ks][3], bh2, bh3);
                mma16816(sacc[2*p+1], ql[ks][0], ql[ks][1], ql[ks][2], ql[ks][3], bh2, bh3);
                mma16816(sacc[2*p+1], qh[ks][0], qh[ks][1], qh[ks][2], qh[ks][3], bl2, bl3);
            }
        }

        // ---- pass 1: + bias, masks, row max (cache lw in regs) ----
        float2 lwc0[8], lwc1[8];
        float rmax0 = -INFINITY, rmax1 = -INFINITY;
#pragma unroll
        for (int nt = 0; nt < 8; nt++) {
            int col = kc + 8 * nt + 2 * tig;
            float2 bb0 = __ldg((const float2*)(biasB + (size_t)(qw + gid)     * SSQ + col));
            float2 bb1 = __ldg((const float2*)(biasB + (size_t)(qw + gid + 8) * SSQ + col));
            lwc0[nt] = __ldg((const float2*)(lwB + (size_t)(qw + gid)     * SSQ + col));
            lwc1[nt] = __ldg((const float2*)(lwB + (size_t)(qw + gid + 8) * SSQ + col));
            float mk0 = maskS[8 * nt + 2 * tig];
            float mk1 = maskS[8 * nt + 2 * tig + 1];
            float v0 = sacc[nt][0] + bb0.x; if (mk0 != 0.f || lwc0[nt].x <= 1e-5f) v0 = -INFINITY;
            float v1 = sacc[nt][1] + bb0.y; if (mk1 != 0.f || lwc0[nt].y <= 1e-5f) v1 = -INFINITY;
            float v2 = sacc[nt][2] + bb1.x; if (mk0 != 0.f || lwc1[nt].x <= 1e-5f) v2 = -INFINITY;
            float v3 = sacc[nt][3] + bb1.y; if (mk1 != 0.f || lwc1[nt].y <= 1e-5f) v3 = -INFINITY;
            sacc[nt][0] = v0; sacc[nt][1] = v1; sacc[nt][2] = v2; sacc[nt][3] = v3;
            rmax0 = fmaxf(rmax0, fmaxf(v0, v1));
            rmax1 = fmaxf(rmax1, fmaxf(v2, v3));
        }
        rmax0 = fmaxf(rmax0, __shfl_xor_sync(0xffffffffu, rmax0, 1));
        rmax0 = fmaxf(rmax0, __shfl_xor_sync(0xffffffffu, rmax0, 2));
        rmax1 = fmaxf(rmax1, __shfl_xor_sync(0xffffffffu, rmax1, 1));
        rmax1 = fmaxf(rmax1, __shfl_xor_sync(0xffffffffu, rmax1, 2));

        float mn0 = fmaxf(m0, rmax0), mn1 = fmaxf(m1, rmax1);
        float sc0 = (mn0 == -INFINITY) ? 1.f : __expf(m0 - mn0);
        float sc1 = (mn1 == -INFINITY) ? 1.f : __expf(m1 - mn1);
        m0 = mn0; m1 = mn1;

        // ---- pass 2: exp, p = e*lw, pack bf16 hi/lo A-frags ----
        float ps0 = 0.f, ps1 = 0.f;
        uint32_t pah[8][2], pal[8][2];
#pragma unroll
        for (int nt = 0; nt < 8; nt++) {
            float e0 = (sacc[nt][0] == -INFINITY) ? 0.f : __expf(sacc[nt][0] - mn0);
            float e1 = (sacc[nt][1] == -INFINITY) ? 0.f : __expf(sacc[nt][1] - mn0);
            float e2 = (sacc[nt][2] == -INFINITY) ? 0.f : __expf(sacc[nt][2] - mn1);
            float e3 = (sacc[nt][3] == -INFINITY) ? 0.f : __expf(sacc[nt][3] - mn1);
            ps0 += e0 + e1; ps1 += e2 + e3;
            float p0 = e0 * lwc0[nt].x, p1 = e1 * lwc0[nt].y;
            float p2 = e2 * lwc1[nt].x, p3 = e3 * lwc1[nt].y;
            __nv_bfloat16 h0, h1, h2, h3, lo0, lo1, lo2, lo3;
            bsplit(p0, h0, lo0); bsplit(p1, h1, lo1);
            bsplit(p2, h2, lo2); bsplit(p3, h3, lo3);
            __nv_bfloat162 t;
            t = __nv_bfloat162(h0, h1);   pah[nt][0] = *(uint32_t*)&t;
            t = __nv_bfloat162(h2, h3);   pah[nt][1] = *(uint32_t*)&t;
            t = __nv_bfloat162(lo0, lo1); pal[nt][0] = *(uint32_t*)&t;
            t = __nv_bfloat162(lo2, lo3); pal[nt][1] = *(uint32_t*)&t;
        }
        ps0 += __shfl_xor_sync(0xffffffffu, ps0, 1);
        ps0 += __shfl_xor_sync(0xffffffffu, ps0, 2);
        ps1 += __shfl_xor_sync(0xffffffffu, ps1, 1);
        ps1 += __shfl_xor_sync(0xffffffffu, ps1, 2);
        l0 = l0 * sc0 + ps0;
        l1 = l1 * sc1 + ps1;

#pragma unroll
        for (int nt = 0; nt < 8; nt++) {
            pacc[nt][0] *= sc0; pacc[nt][1] *= sc0;
            pacc[nt][2] *= sc1; pacc[nt][3] *= sc1;
        }

        // ---- PV (3-pass bf16x2, ldmatrix B-frags from transposed V) ----
#pragma unroll
        for (int ks = 0; ks < 4; ks++) {
            uint32_t ah0 = pah[2*ks][0],   ah1 = pah[2*ks][1];
            uint32_t ah2 = pah[2*ks+1][0], ah3 = pah[2*ks+1][1];
            uint32_t al0 = pal[2*ks][0],   al1 = pal[2*ks][1];
            uint32_t al2 = pal[2*ks+1][0], al3 = pal[2*ks+1][1];
#pragma unroll
            for (int p = 0; p < 4; p++) {
                uint32_t off = lanoff + (uint32_t)(p * 2304 + ks * 32);
                uint32_t vh0, vh1, vh2, vh3, vl0, vl1, vl2, vl3;
                ldsm4(vbHi + off, vh0, vh1, vh2, vh3);
                ldsm4(vbLo + off, vl0, vl1, vl2, vl3);
                mma16816(pacc[2*p],   ah0, ah1, ah2, ah3, vh0, vh1);
                mma16816(pacc[2*p],   al0, al1, al2, al3, vh0, vh1);
                mma16816(pacc[2*p],   ah0, ah1, ah2, ah3, vl0, vl1);
                mma16816(pacc[2*p+1], ah0, ah1, ah2, ah3, vh2, vh3);
                mma16816(pacc[2*p+1], al0, al1, al2, al3, vh2, vh3);
                mma16816(pacc[2*p+1], ah0, ah1, ah2, ah3, vl2, vl3);
            }
        }
        __syncthreads();
    }

    // ---- epilogue ----
    float inv0 = 1.f / l0, inv1 = 1.f / l1;
#pragma unroll
    for (int nt = 0; nt < 8; nt++) {
        int d = 8 * nt + 2 * tig;
        size_t o0 = (size_t)(b * TT + q0 + qw + gid)     * HHC + h * HDD + d;
        size_t o1 = (size_t)(b * TT + q0 + qw + gid + 8) * HHC + h * HDD + d;
        *(float2*)(g_att + o0) = make_float2(pacc[nt][0] * inv0, pacc[nt][1] * inv0);
        *(float2*)(g_att + o1) = make_float2(pacc[nt][2] * inv1, pacc[nt][3] * inv1);
    }
}

// ---------------- LayerNorm over H=1024 ----------------
__global__ __launch_bounds__(256) void ln_kernel(
    const float* __restrict__ gam, const float* __restrict__ bet)
{
    __shared__ float red[2][32];
    int row = blockIdx.x;
    const float* x = g_att + (size_t)row * HHC;
    float v[4], s = 0.f, sq = 0.f;
#pragma unroll
    for (int i = 0; i < 4; i++) {
        v[i] = x[threadIdx.x + i * 256];
        s += v[i]; sq += v[i] * v[i];
    }
#pragma unroll
    for (int o = 16; o; o >>= 1) {
        s  += __shfl_xor_sync(0xffffffffu, s,  o);
        sq += __shfl_xor_sync(0xffffffffu, sq, o);
    }
    int lane = threadIdx.x & 31, w = threadIdx.x >> 5;
    if (lane == 0) { red[0][w] = s; red[1][w] = sq; }
    __syncthreads();
    if (w == 0) {
        s  = (lane < 8) ? red[0][lane] : 0.f;
        sq = (lane < 8) ? red[1][lane] : 0.f;
#pragma unroll
        for (int o = 4; o; o >>= 1) {
            s  += __shfl_xor_sync(0xffffffffu, s,  o);
            sq += __shfl_xor_sync(0xffffffffu, sq, o);
        }
        if (lane == 0) { red[0][0] = s; red[1][0] = sq; }
    }
    __syncthreads();
    float mu  = red[0][0] * (1.f / HHC);
    float var = red[1][0] * (1.f / HHC) - mu * mu;
    float rs  = rsqrtf(var + LN_EPS);
#pragma unroll
    for (int i = 0; i < 4; i++) {
        int c = threadIdx.x + i * 256;
        g_ln[(size_t)row * HHC + c] = (v[i] - mu) * rs * gam[c] + bet[c];
    }
}

// ---------------- launch ----------------
extern "C" void kernel_launch(void* const* d_in, const int* in_sizes, int n_in,
                              void* d_out, int out_size)
{
    const float* x    = (const float*)d_in[0];
    const float* bias = (const float*)d_in[1];
    const float* lw   = (const float*)d_in[2];
    const unsigned char* kpm = (const unsigned char*)d_in[3];
    const int*   outcell = (const int*)d_in[4];
    const unsigned char* epm = (const unsigned char*)d_in[5];
    const float* wq  = (const float*)d_in[6];
    const float* wk  = (const float*)d_in[7];
    const float* wv  = (const float*)d_in[8];
    const float* wo  = (const float*)d_in[9];
    const float* lng = (const float*)d_in[10];
    const float* lnb = (const float*)d_in[11];
    float* out = (float*)d_out;

    float *Q, *K, *V, *LN;
    cudaGetSymbolAddress((void**)&Q,  g_Q);
    cudaGetSymbolAddress((void**)&K,  g_K);
    cudaGetSymbolAddress((void**)&V,  g_V);
    cudaGetSymbolAddress((void**)&LN, g_ln);

    dim3 gg(HHC / 128, (BB * TT) / 128);
    gemm_tf32_nt<<<gg, 256>>>(x, wq, Q, BB * TT, HHC, HHC, SCALING);
    gemm_tf32_nt<<<gg, 256>>>(x, wk, K, BB * TT, HHC, HHC, 1.f);
    gemm_tf32_nt<<<gg, 256>>>(x, wv, V, BB * TT, HHC, HHC, 1.f);

    rope_q_kernel<<<(BB * TT * NHH * 32) / 256, 256>>>();
    gather_k_kernel<<<(BB * SSQ * NHH * 32) / 256, 256>>>(outcell);
    gather_vt_kernel<<<BB * NHH * HDD * 6, 256>>>(outcell);

    cudaFuncSetAttribute(attn_mma_kernel, cudaFuncAttributeMaxDynamicSharedMemorySize, ATT_SMEM);
    attn_mma_kernel<<<dim3(TT / 128, NHH, BB), 256, ATT_SMEM>>>(bias, lw, kpm, epm);

    ln_kernel<<<BB * TT, 256>>>(lng, lnb);

    gemm_tf32_nt<<<gg, 256>>>(LN, wo, out, BB * TT, HHC, HHC, 1.f);
}

// round 8
// speedup vs baseline: 1.2777x; 1.2777x over previous
#include <cuda_runtime.h>
#include <cuda_bf16.h>
#include <cstdint>

// Problem constants
#define BB   4
#define TT   1024
#define EE   512
#define SSQ  1536   // S = T + E
#define HHC  1024   // hidden
#define NHH  16
#define HDD  64
#define LN_EPS 1e-5f
#define SCALING 0.125f   // sqrt(64)/64

// -log2(10000)/32
#define NLOG2F_STEP (-0.4152410118609203f)

// ---------------- scratch ----------------
__device__ float g_Q  [BB*TT*HHC];    // rope'd Q, [B,T,H]
__device__ float g_K  [BB*TT*HHC];    // raw K projection
__device__ float g_V  [BB*TT*HHC];    // raw V projection
__device__ float g_att[BB*TT*HHC];    // attention out pre-LN
__device__ float g_ln [BB*TT*HHC];    // LN output
// bf16 hi/lo split K (gathered+rope'd), [B,S,H]
__device__ __nv_bfloat16 g_Khi[BB*SSQ*HHC];
__device__ __nv_bfloat16 g_Klo[BB*SSQ*HHC];
// bf16 hi/lo split V, transposed per head: [B*NH, HD, S]
__device__ __nv_bfloat16 g_Vthi[BB*NHH*HDD*SSQ];
__device__ __nv_bfloat16 g_Vtlo[BB*NHH*HDD*SSQ];

// ---------------- helpers ----------------
__device__ __forceinline__ uint32_t f2tf(float f) {
    uint32_t u; asm("cvt.rna.tf32.f32 %0, %1;" : "=r"(u) : "f"(f)); return u;
}

__device__ __forceinline__ void bsplit(float x, __nv_bfloat16& h, __nv_bfloat16& l) {
    h = __float2bfloat16_rn(x);
    l = __float2bfloat16_rn(x - __bfloat162float(h));
}

__device__ __forceinline__ void mma16816(float* c,
    uint32_t a0, uint32_t a1, uint32_t a2, uint32_t a3,
    uint32_t b0, uint32_t b1)
{
    asm volatile(
        "mma.sync.aligned.m16n8k16.row.col.f32.bf16.bf16.f32 "
        "{%0,%1,%2,%3},{%4,%5,%6,%7},{%8,%9},{%0,%1,%2,%3};"
        : "+f"(c[0]), "+f"(c[1]), "+f"(c[2]), "+f"(c[3])
        : "r"(a0), "r"(a1), "r"(a2), "r"(a3), "r"(b0), "r"(b1));
}

__device__ __forceinline__ void ldsm4(uint32_t addr,
    uint32_t& r0, uint32_t& r1, uint32_t& r2, uint32_t& r3)
{
    asm volatile("ldmatrix.sync.aligned.m8n8.x4.shared.b16 {%0,%1,%2,%3}, [%4];"
        : "=r"(r0), "=r"(r1), "=r"(r2), "=r"(r3) : "r"(addr));
}

__device__ __forceinline__ void cpa16(uint32_t daddr, const void* src) {
    asm volatile("cp.async.cg.shared.global [%0], [%1], 16;" :: "r"(daddr), "l"(src));
}
#define CP_COMMIT asm volatile("cp.async.commit_group;")
#define CP_WAIT1  asm volatile("cp.async.wait_group 1;")
#define CP_WAIT0  asm volatile("cp.async.wait_group 0;")

// ---------------- GEMM: C[M,N] = alpha * A[M,K] * B[N,K]^T (tf32 mma.sync) ----------------
__global__ __launch_bounds__(256) void gemm_tf32_nt(
    const float* __restrict__ A, const float* __restrict__ Bm,
    float* __restrict__ C, int M, int N, int K, float alpha)
{
    __shared__ uint32_t As[128 * 36];
    __shared__ uint32_t Bs[128 * 36];

    const int tid  = threadIdx.x;
    const int lane = tid & 31;
    const int wid  = tid >> 5;
    const int gid  = lane >> 2;
    const int tig  = lane & 3;
    const int wm   = (wid & 1) * 64;
    const int wn   = (wid >> 1) * 32;
    const int bm   = blockIdx.y * 128;
    const int bn   = blockIdx.x * 128;

    float acc[4][4][4];
#pragma unroll
    for (int i = 0; i < 4; i++)
#pragma unroll
        for (int j = 0; j < 4; j++)
#pragma unroll
            for (int r = 0; r < 4; r++) acc[i][j][r] = 0.f;

    for (int kt = 0; kt < K; kt += 32) {
#pragma unroll
        for (int it = 0; it < 4; it++) {
            int f4 = tid + it * 256;
            int r  = f4 >> 3;
            int c  = (f4 & 7) << 2;
            float4 a = *reinterpret_cast<const float4*>(A + (size_t)(bm + r) * K + kt + c);
            uint32_t* d = &As[r * 36 + c];
            d[0] = f2tf(a.x); d[1] = f2tf(a.y); d[2] = f2tf(a.z); d[3] = f2tf(a.w);
            float4 b = *reinterpret_cast<const float4*>(Bm + (size_t)(bn + r) * K + kt + c);
            uint32_t* e = &Bs[r * 36 + c];
            e[0] = f2tf(b.x); e[1] = f2tf(b.y); e[2] = f2tf(b.z); e[3] = f2tf(b.w);
        }
        __syncthreads();
#pragma unroll
        for (int ks = 0; ks < 32; ks += 8) {
            uint32_t af[4][4], bf[4][2];
#pragma unroll
            for (int mt = 0; mt < 4; mt++) {
                const uint32_t* p = &As[(wm + mt * 16 + gid) * 36 + ks + tig];
                af[mt][0] = p[0];
                af[mt][1] = p[8 * 36];
                af[mt][2] = p[4];
                af[mt][3] = p[8 * 36 + 4];
            }
#pragma unroll
            for (int nt = 0; nt < 4; nt++) {
                const uint32_t* p = &Bs[(wn + nt * 8 + gid) * 36 + ks + tig];
                bf[nt][0] = p[0];
                bf[nt][1] = p[4];
            }
#pragma unroll
            for (int mt = 0; mt < 4; mt++)
#pragma unroll
                for (int nt = 0; nt < 4; nt++)
                    asm volatile(
                        "mma.sync.aligned.m16n8k8.row.col.f32.tf32.tf32.f32 "
                        "{%0,%1,%2,%3},{%4,%5,%6,%7},{%8,%9},{%0,%1,%2,%3};"
                        : "+f"(acc[mt][nt][0]), "+f"(acc[mt][nt][1]),
                          "+f"(acc[mt][nt][2]), "+f"(acc[mt][nt][3])
                        : "r"(af[mt][0]), "r"(af[mt][1]), "r"(af[mt][2]), "r"(af[mt][3]),
                          "r"(bf[nt][0]), "r"(bf[nt][1]));
        }
        __syncthreads();
    }

#pragma unroll
    for (int mt = 0; mt < 4; mt++) {
#pragma unroll
        for (int nt = 0; nt < 4; nt++) {
            int r0 = bm + wm + mt * 16 + gid;
            int c0 = bn + wn + nt * 8 + tig * 2;
            float2 v01 = make_float2(acc[mt][nt][0] * alpha, acc[mt][nt][1] * alpha);
            float2 v23 = make_float2(acc[mt][nt][2] * alpha, acc[mt][nt][3] * alpha);
            *reinterpret_cast<float2*>(C + (size_t)r0 * N + c0)       = v01;
            *reinterpret_cast<float2*>(C + (size_t)(r0 + 8) * N + c0) = v23;
        }
    }
}

// ---------------- RoPE on Q (in place), fp32 math ----------------
__global__ __launch_bounds__(256) void rope_q_kernel()
{
    int idx = blockIdx.x * blockDim.x + threadIdx.x;
    int i    = idx & 31;
    int head = (idx >> 5) & (NHH - 1);
    int row  = idx >> 9;
    int t    = row & (TT - 1);
    float* p = g_Q + (size_t)row * HHC + head * HDD + i;
    float x1 = p[0], x2 = p[32];
    float invf = exp2f(NLOG2F_STEP * (float)i);
    float arg = (float)t * invf;
    float s, c; sincosf(arg, &s, &c);
    p[0]  = x1 * c - x2 * s;
    p[32] = x2 * c + x1 * s;
}

// ---------------- Gather K + RoPE, write bf16 hi/lo [B,S,H] ----------------
__global__ __launch_bounds__(256) void gather_k_kernel(const int* __restrict__ outcell)
{
    int idx = blockIdx.x * blockDim.x + threadIdx.x;
    int i    = idx & 31;
    int head = (idx >> 5) & (NHH - 1);
    int rest = idx >> 9;
    int s    = rest % SSQ;
    int b    = rest / SSQ;
    int src  = (s < TT) ? s : outcell[b * EE + (s - TT)];

    size_t soff = (size_t)(b * TT + src) * HHC + head * HDD + i;
    size_t doff = (size_t)(b * SSQ + s) * HHC + head * HDD + i;

    float k1 = g_K[soff], k2 = g_K[soff + 32];
    float invf = exp2f(NLOG2F_STEP * (float)i);
    float arg = (float)s * invf;
    float sn, cs; sincosf(arg, &sn, &cs);
    float r1 = k1 * cs - k2 * sn;
    float r2 = k2 * cs + k1 * sn;
    __nv_bfloat16 hh, ll;
    bsplit(r1, hh, ll); g_Khi[doff]      = hh; g_Klo[doff]      = ll;
    bsplit(r2, hh, ll); g_Khi[doff + 32] = hh; g_Klo[doff + 32] = ll;
}

// ---------------- Gather V transposed via smem (coalesced both sides) ----------------
// grid (SSQ/64, B*NH), 256 threads. Tile: 64 s  x 64 d.
__global__ __launch_bounds__(256) void gather_vt_kernel(const int* __restrict__ outcell)
{
    __shared__ float ts[64][65];
    const int tid = threadIdx.x;
    const int s0  = blockIdx.x * 64;
    const int bh  = blockIdx.y;
    const int b   = bh >> 4, h = bh & (NHH - 1);

    // read: coalesced rows of g_V (64 consecutive d per s)
#pragma unroll
    for (int it = 0; it < 16; it++) {
        int sl = it * 4 + (tid >> 6);
        int d  = tid & 63;
        int s  = s0 + sl;
        int src = (s < TT) ? s : outcell[b * EE + (s - TT)];
        ts[d][sl] = g_V[(size_t)(b * TT + src) * HHC + h * HDD + d];
    }
    __syncthreads();

    // write: thread owns (d = tid>>2, 16 s values), 16B vectorized bf16 stores
    int d  = tid >> 2;
    int sq = (tid & 3) * 16;
    uint32_t phi[8], plo[8];
#pragma unroll
    for (int j = 0; j < 8; j++) {
        __nv_bfloat16 h0, l0, h1, l1;
        bsplit(ts[d][sq + 2*j],     h0, l0);
        bsplit(ts[d][sq + 2*j + 1], h1, l1);
        __nv_bfloat162 th(h0, h1), tl(l0, l1);
        phi[j] = *(uint32_t*)&th;
        plo[j] = *(uint32_t*)&tl;
    }
    size_t o = (size_t)(bh * HDD + d) * SSQ + s0 + sq;
    *(uint4*)(g_Vthi + o)     = make_uint4(phi[0], phi[1], phi[2], phi[3]);
    *(uint4*)(g_Vthi + o + 8) = make_uint4(phi[4], phi[5], phi[6], phi[7]);
    *(uint4*)(g_Vtlo + o)     = make_uint4(plo[0], plo[1], plo[2], plo[3]);
    *(uint4*)(g_Vtlo + o + 8) = make_uint4(plo[4], plo[5], plo[6], plo[7]);
}

// ---------------- Attention: flash, bf16x2-split mma, cp.async double-buffer ----------------
// SMEM bf16 layout (bytes):
//   Qhi  [128][72] @ 0       (18432)
//   Qlo  [128][72] @ 18432   (18432)
//   buf{0,1} @ 36864 + sel*36864, each:
//     Khi [64][72] +0, Klo +9216, Vthi +18432, Vtlo +27648   (9216 each)
//   maskS (64 floats) @ 110592
#define ATT_SMEM 110848
__global__ __launch_bounds__(256, 1) void attn_mma_kernel(
    const float* __restrict__ bias, const float* __restrict__ lw,
    const unsigned char* __restrict__ keypad, const unsigned char* __restrict__ expand)
{
    extern __shared__ char smraw[];
    __nv_bfloat16* sb = (__nv_bfloat16*)smraw;
    float* maskS = (float*)(smraw + 110592);
    const uint32_t sbase = (uint32_t)__cvta_generic_to_shared(smraw);

    const int tid  = threadIdx.x;
    const int lane = tid & 31;
    const int w    = tid >> 5;
    const int gid  = lane >> 2;
    const int tig  = lane & 3;
    const int h = blockIdx.y, b = blockIdx.z;
    const int bh = b * NHH + h;
    const int q0 = blockIdx.x * 128;
    const int qw = w * 16;

    const __nv_bfloat16* gKhi  = g_Khi  + (size_t)b * SSQ * HHC + h * HDD;
    const __nv_bfloat16* gKlo  = g_Klo  + (size_t)b * SSQ * HHC + h * HDD;
    const __nv_bfloat16* gVthi = g_Vthi + (size_t)bh * HDD * SSQ;
    const __nv_bfloat16* gVtlo = g_Vtlo + (size_t)bh * HDD * SSQ;

    // ---- issue tile kc into buffer sel (all threads) ----
    auto issue_tile = [&](int kc, int sel) {
        uint32_t bbase = sbase + 36864u + (uint32_t)sel * 36864u;
#pragma unroll
        for (int half = 0; half < 2; half++) {
            int chunk = tid + half * 256;       // 0..511
            int row = chunk >> 3;               // 0..63
            int ce  = (chunk & 7) * 8;          // bf16 offset 0..56
            uint32_t so = (uint32_t)(row * 72 + ce) * 2;
            cpa16(bbase + so,          gKhi  + (size_t)(kc + row) * HHC + ce);
            cpa16(bbase + 9216u + so,  gKlo  + (size_t)(kc + row) * HHC + ce);
            cpa16(bbase + 18432u + so, gVthi + (size_t)row * SSQ + kc + ce);
            cpa16(bbase + 27648u + so, gVtlo + (size_t)row * SSQ + kc + ce);
        }
        CP_COMMIT;
    };

    issue_tile(0, 0);

    // ---- stage Q (split to bf16 hi/lo) ----
    __nv_bfloat16* Qhi = sb;
    __nv_bfloat16* Qlo = sb + 9216;
#pragma unroll
    for (int it = 0; it < 8; it++) {
        int f4 = tid + it * 256;
        int r  = f4 >> 4;
        int c  = (f4 & 15) * 4;
        float4 v = *(const float4*)(g_Q + (size_t)(b * TT + q0 + r) * HHC + h * HDD + c);
        __nv_bfloat16 hh, ll;
        bsplit(v.x, hh, ll); Qhi[r*72+c+0] = hh; Qlo[r*72+c+0] = ll;
        bsplit(v.y, hh, ll); Qhi[r*72+c+1] = hh; Qlo[r*72+c+1] = ll;
        bsplit(v.z, hh, ll); Qhi[r*72+c+2] = hh; Qlo[r*72+c+2] = ll;
        bsplit(v.w, hh, ll); Qhi[r*72+c+3] = hh; Qlo[r*72+c+3] = ll;
    }
    __syncthreads();

    // ---- Q fragments (resident) ----
    uint32_t qh[4][4], ql[4][4];
#pragma unroll
    for (int ks = 0; ks < 4; ks++) {
        int c0 = 2 * tig + 16 * ks;
        qh[ks][0] = *(uint32_t*)&Qhi[(qw + gid)     * 72 + c0];
        qh[ks][1] = *(uint32_t*)&Qhi[(qw + gid + 8) * 72 + c0];
        qh[ks][2] = *(uint32_t*)&Qhi[(qw + gid)     * 72 + c0 + 8];
        qh[ks][3] = *(uint32_t*)&Qhi[(qw + gid + 8) * 72 + c0 + 8];
        ql[ks][0] = *(uint32_t*)&Qlo[(qw + gid)     * 72 + c0];
        ql[ks][1] = *(uint32_t*)&Qlo[(qw + gid + 8) * 72 + c0];
        ql[ks][2] = *(uint32_t*)&Qlo[(qw + gid)     * 72 + c0 + 8];
        ql[ks][3] = *(uint32_t*)&Qlo[(qw + gid + 8) * 72 + c0 + 8];
    }

    float m0 = -INFINITY, m1 = -INFINITY, l0 = 0.f, l1 = 0.f;
    float pacc[8][4];
#pragma unroll
    for (int nt = 0; nt < 8; nt++)
#pragma unroll
        for (int c = 0; c < 4; c++) pacc[nt][c] = 0.f;

    const float* biasB = bias + ((size_t)(b * NHH + h) * TT + q0) * SSQ;
    const float* lwB   = lw   + ((size_t)b * TT + q0) * SSQ;

    // ldmatrix per-lane offset within a [rows][72] bf16 array (bytes)
    const uint32_t lanoff =
        (uint32_t)((((lane >> 4) & 1) * 8 + (lane & 7)) * 72 + ((lane >> 3) & 1) * 8) * 2;

    for (int i = 0; i < 24; i++) {
        const int kc = i * 64;
        const int cur = i & 1;
        if (i < 23) issue_tile(kc + 64, cur ^ 1);
        if (i < 23) { CP_WAIT1; } else { CP_WAIT0; }
        if (tid < 64) {
            int s = kc + tid;
            unsigned char mk = (s < TT) ? keypad[b * TT + s] : expand[b * EE + (s - TT)];
            maskS[tid] = mk ? 1.f : 0.f;
        }
        __syncthreads();

        const uint32_t kbHi = sbase + 36864u + (uint32_t)cur * 36864u;
        const uint32_t kbLo = kbHi + 9216u;
        const uint32_t vbHi = kbHi + 18432u;
        const uint32_t vbLo = kbHi + 27648u;

        // ---- QK^T (3-pass bf16x2, ldmatrix B-frags) ----
        float sacc[8][4];
#pragma unroll
        for (int nt = 0; nt < 8; nt++)
#pragma unroll
            for (int c = 0; c < 4; c++) sacc[nt][c] = 0.f;

#pragma unroll
        for (int ks = 0; ks < 4; ks++) {
#pragma unroll
            for (int p = 0; p < 4; p++) {
                uint32_t off = lanoff + (uint32_t)(p * 2304 + ks * 32);
                uint32_t bh0, bh1, bh2, bh3, bl0, bl1, bl2, bl3;
                ldsm4(kbHi + off, bh0, bh1, bh2, bh3);
                ldsm4(kbLo + off, bl0, bl1, bl2, bl3);
                mma16816(sacc[2*p],   qh[ks][0], qh[ks][1], qh[ks][2], qh[ks][3], bh0, bh1);
                mma16816(sacc[2*p],   ql[ks][0], ql[ks][1], ql[ks][2], ql[ks][3], bh0, bh1);
                mma16816(sacc[2*p],   qh[ks][0], qh[ks][1], qh[ks][2], qh[ks][3], bl0, bl1);
                mma16816(sacc[2*p+1], qh[ks][0], qh[ks][1], qh[ks][2], qh[ks][3], bh2, bh3);
                mma16816(sacc[2*p+1], ql[ks][0], ql[ks][1], ql[ks][2], ql[ks][3], bh2, bh3);
                mma16816(sacc[2*p+1], qh[ks][0], qh[ks][1], qh[ks][2], qh[ks][3], bl2, bl3);
            }
        }

        // ---- pass 1: + bias, masks, row max (no lw caching: reload later) ----
        float rmax0 = -INFINITY, rmax1 = -INFINITY;
#pragma unroll
        for (int nt = 0; nt < 8; nt++) {
            int col = kc + 8 * nt + 2 * tig;
            float2 bb0 = __ldg((const float2*)(biasB + (size_t)(qw + gid)     * SSQ + col));
            float2 bb1 = __ldg((const float2*)(biasB + (size_t)(qw + gid + 8) * SSQ + col));
            float2 w0  = __ldg((const float2*)(lwB   + (size_t)(qw + gid)     * SSQ + col));
            float2 w1  = __ldg((const float2*)(lwB   + (size_t)(qw + gid + 8) * SSQ + col));
            float mk0 = maskS[8 * nt + 2 * tig];
            float mk1 = maskS[8 * nt + 2 * tig + 1];
            float v0 = sacc[nt][0] + bb0.x; if (mk0 != 0.f || w0.x <= 1e-5f) v0 = -INFINITY;
            float v1 = sacc[nt][1] + bb0.y; if (mk1 != 0.f || w0.y <= 1e-5f) v1 = -INFINITY;
            float v2 = sacc[nt][2] + bb1.x; if (mk0 != 0.f || w1.x <= 1e-5f) v2 = -INFINITY;
            float v3 = sacc[nt][3] + bb1.y; if (mk1 != 0.f || w1.y <= 1e-5f) v3 = -INFINITY;
            sacc[nt][0] = v0; sacc[nt][1] = v1; sacc[nt][2] = v2; sacc[nt][3] = v3;
            rmax0 = fmaxf(rmax0, fmaxf(v0, v1));
            rmax1 = fmaxf(rmax1, fmaxf(v2, v3));
        }
        rmax0 = fmaxf(rmax0, __shfl_xor_sync(0xffffffffu, rmax0, 1));
        rmax0 = fmaxf(rmax0, __shfl_xor_sync(0xffffffffu, rmax0, 2));
        rmax1 = fmaxf(rmax1, __shfl_xor_sync(0xffffffffu, rmax1, 1));
        rmax1 = fmaxf(rmax1, __shfl_xor_sync(0xffffffffu, rmax1, 2));

        float mn0 = fmaxf(m0, rmax0), mn1 = fmaxf(m1, rmax1);
        float sc0 = (mn0 == -INFINITY) ? 1.f : __expf(m0 - mn0);
        float sc1 = (mn1 == -INFINITY) ? 1.f : __expf(m1 - mn1);
        m0 = mn0; m1 = mn1;

#pragma unroll
        for (int nt = 0; nt < 8; nt++) {
            pacc[nt][0] *= sc0; pacc[nt][1] *= sc0;
            pacc[nt][2] *= sc1; pacc[nt][3] *= sc1;
        }

        // ---- fused pass 2 + PV: per k-slice, exp/pack transiently then 8 mma ----
        float ps0 = 0.f, ps1 = 0.f;
#pragma unroll
        for (int ks = 0; ks < 4; ks++) {
            uint32_t ah[4], al[4];
#pragma unroll
            for (int j = 0; j < 2; j++) {
                int nt = 2 * ks + j;
                int col = kc + 8 * nt + 2 * tig;
                float2 w0 = __ldg((const float2*)(lwB + (size_t)(qw + gid)     * SSQ + col));
                float2 w1 = __ldg((const float2*)(lwB + (size_t)(qw + gid + 8) * SSQ + col));
                float e0 = (sacc[nt][0] == -INFINITY) ? 0.f : __expf(sacc[nt][0] - mn0);
                float e1 = (sacc[nt][1] == -INFINITY) ? 0.f : __expf(sacc[nt][1] - mn0);
                float e2 = (sacc[nt][2] == -INFINITY) ? 0.f : __expf(sacc[nt][2] - mn1);
                float e3 = (sacc[nt][3] == -INFINITY) ? 0.f : __expf(sacc[nt][3] - mn1);
                ps0 += e0 + e1; ps1 += e2 + e3;
                float p0 = e0 * w0.x, p1 = e1 * w0.y;
                float p2 = e2 * w1.x, p3 = e3 * w1.y;
                __nv_bfloat16 h0, h1, h2, h3, lo0, lo1, lo2, lo3;
                bsplit(p0, h0, lo0); bsplit(p1, h1, lo1);
                bsplit(p2, h2, lo2); bsplit(p3, h3, lo3);
                __nv_bfloat162 t;
                t = __nv_bfloat162(h0, h1);   ah[2*j]     = *(uint32_t*)&t;
                t = __nv_bfloat162(h2, h3);   ah[2*j + 1] = *(uint32_t*)&t;
                t = __nv_bfloat162(lo0, lo1); al[2*j]     = *(uint32_t*)&t;
                t = __nv_bfloat162(lo2, lo3); al[2*j + 1] = *(uint32_t*)&t;
            }
#pragma unroll
            for (int p = 0; p < 4; p++) {
                uint32_t off = lanoff + (uint32_t)(p * 2304 + ks * 32);
                uint32_t vh0, vh1, vh2, vh3, vl0, vl1, vl2, vl3;
                ldsm4(vbHi + off, vh0, vh1, vh2, vh3);
                ldsm4(vbLo + off, vl0, vl1, vl2, vl3);
                mma16816(pacc[2*p],   ah[0], ah[1], ah[2], ah[3], vh0, vh1);
                mma16816(pacc[2*p],   al[0], al[1], al[2], al[3], vh0, vh1);
                mma16816(pacc[2*p],   ah[0], ah[1], ah[2], ah[3], vl0, vl1);
                mma16816(pacc[2*p+1], ah[0], ah[1], ah[2], ah[3], vh2, vh3);
                mma16816(pacc[2*p+1], al[0], al[1], al[2], al[3], vh2, vh3);
                mma16816(pacc[2*p+1], ah[0], ah[1], ah[2], ah[3], vl2, vl3);
            }
        }
        ps0 += __shfl_xor_sync(0xffffffffu, ps0, 1);
        ps0 += __shfl_xor_sync(0xffffffffu, ps0, 2);
        ps1 += __shfl_xor_sync(0xffffffffu, ps1, 1);
        ps1 += __shfl_xor_sync(0xffffffffu, ps1, 2);
        l0 = l0 * sc0 + ps0;
        l1 = l1 * sc1 + ps1;
        __syncthreads();
    }

    // ---- epilogue ----
    float inv0 = 1.f / l0, inv1 = 1.f / l1;
#pragma unroll
    for (int nt = 0; nt < 8; nt++) {
        int d = 8 * nt + 2 * tig;
        size_t o0 = (size_t)(b * TT + q0 + qw + gid)     * HHC + h * HDD + d;
        size_t o1 = (size_t)(b * TT + q0 + qw + gid + 8) * HHC + h * HDD + d;
        *(float2*)(g_att + o0) = make_float2(pacc[nt][0] * inv0, pacc[nt][1] * inv0);
        *(float2*)(g_att + o1) = make_float2(pacc[nt][2] * inv1, pacc[nt][3] * inv1);
    }
}

// ---------------- LayerNorm over H=1024 ----------------
__global__ __launch_bounds__(256) void ln_kernel(
    const float* __restrict__ gam, const float* __restrict__ bet)
{
    __shared__ float red[2][32];
    int row = blockIdx.x;
    const float* x = g_att + (size_t)row * HHC;
    float v[4], s = 0.f, sq = 0.f;
#pragma unroll
    for (int i = 0; i < 4; i++) {
        v[i] = x[threadIdx.x + i * 256];
        s += v[i]; sq += v[i] * v[i];
    }
#pragma unroll
    for (int o = 16; o; o >>= 1) {
        s  += __shfl_xor_sync(0xffffffffu, s,  o);
        sq += __shfl_xor_sync(0xffffffffu, sq, o);
    }
    int lane = threadIdx.x & 31, w = threadIdx.x >> 5;
    if (lane == 0) { red[0][w] = s; red[1][w] = sq; }
    __syncthreads();
    if (w == 0) {
        s  = (lane < 8) ? red[0][lane] : 0.f;
        sq = (lane < 8) ? red[1][lane] : 0.f;
#pragma unroll
        for (int o = 4; o; o >>= 1) {
            s  += __shfl_xor_sync(0xffffffffu, s,  o);
            sq += __shfl_xor_sync(0xffffffffu, sq, o);
        }
        if (lane == 0) { red[0][0] = s; red[1][0] = sq; }
    }
    __syncthreads();
    float mu  = red[0][0] * (1.f / HHC);
    float var = red[1][0] * (1.f / HHC) - mu * mu;
    float rs  = rsqrtf(var + LN_EPS);
#pragma unroll
    for (int i = 0; i < 4; i++) {
        int c = threadIdx.x + i * 256;
        g_ln[(size_t)row * HHC + c] = (v[i] - mu) * rs * gam[c] + bet[c];
    }
}

// ---------------- launch ----------------
extern "C" void kernel_launch(void* const* d_in, const int* in_sizes, int n_in,
                              void* d_out, int out_size)
{
    const float* x    = (const float*)d_in[0];
    const float* bias = (const float*)d_in[1];
    const float* lw   = (const float*)d_in[2];
    const unsigned char* kpm = (const unsigned char*)d_in[3];
    const int*   outcell = (const int*)d_in[4];
    const unsigned char* epm = (const unsigned char*)d_in[5];
    const float* wq  = (const float*)d_in[6];
    const float* wk  = (const float*)d_in[7];
    const float* wv  = (const float*)d_in[8];
    const float* wo  = (const float*)d_in[9];
    const float* lng = (const float*)d_in[10];
    const float* lnb = (const float*)d_in[11];
    float* out = (float*)d_out;

    float *Q, *K, *V, *LN;
    cudaGetSymbolAddress((void**)&Q,  g_Q);
    cudaGetSymbolAddress((void**)&K,  g_K);
    cudaGetSymbolAddress((void**)&V,  g_V);
    cudaGetSymbolAddress((void**)&LN, g_ln);

    dim3 gg(HHC / 128, (BB * TT) / 128);
    gemm_tf32_nt<<<gg, 256>>>(x, wq, Q, BB * TT, HHC, HHC, SCALING);
    gemm_tf32_nt<<<gg, 256>>>(x, wk, K, BB * TT, HHC, HHC, 1.f);
    gemm_tf32_nt<<<gg, 256>>>(x, wv, V, BB * TT, HHC, HHC, 1.f);

    rope_q_kernel<<<(BB * TT * NHH * 32) / 256, 256>>>();
    gather_k_kernel<<<(BB * SSQ * NHH * 32) / 256, 256>>>(outcell);
    gather_vt_kernel<<<dim3(SSQ / 64, BB * NHH), 256>>>(outcell);

    cudaFuncSetAttribute(attn_mma_kernel, cudaFuncAttributeMaxDynamicSharedMemorySize, ATT_SMEM);
    attn_mma_kernel<<<dim3(TT / 128, NHH, BB), 256, ATT_SMEM>>>(bias, lw, kpm, epm);

    ln_kernel<<<BB * TT, 256>>>(lng, lnb);

    gemm_tf32_nt<<<gg, 256>>>(LN, wo, out, BB * TT, HHC, HHC, 1.f);
}

// round 10
// speedup vs baseline: 1.5824x; 1.2385x over previous
#include <cuda_runtime.h>
#include <cuda_fp16.h>
#include <cstdint>

// Problem constants
#define BB   4
#define TT   1024
#define EE   512
#define SSQ  1536   // S = T + E
#define HHC  1024   // hidden
#define NHH  16
#define HDD  64
#define LN_EPS 1e-5f
#define SCALING 0.125f   // sqrt(64)/64

// -log2(10000)/32
#define NLOG2F_STEP (-0.4152410118609203f)

// ---------------- scratch ----------------
__device__ float g_Q  [BB*TT*HHC];    // rope'd Q, [B,T,H]
__device__ float g_K  [BB*TT*HHC];    // raw K projection
__device__ float g_V  [BB*TT*HHC];    // raw V projection
__device__ float g_att[BB*TT*HHC];    // attention out pre-LN
__device__ float g_ln [BB*TT*HHC];    // LN output
// fp16 hi/lo split K (gathered+rope'd), [B,S,H]
__device__ __half g_Khi[BB*SSQ*HHC];
__device__ __half g_Klo[BB*SSQ*HHC];
// fp16 hi/lo split V, transposed per head: [B*NH, HD, S]
__device__ __half g_Vthi[BB*NHH*HDD*SSQ];
__device__ __half g_Vtlo[BB*NHH*HDD*SSQ];

// ---------------- helpers ----------------
__device__ __forceinline__ uint32_t f2tf(float f) {
    uint32_t u; asm("cvt.rna.tf32.f32 %0, %1;" : "=r"(u) : "f"(f)); return u;
}

__device__ __forceinline__ void hsplit(float x, __half& h, __half& l) {
    h = __float2half_rn(x);
    l = __float2half_rn(x - __half2float(h));
}

__device__ __forceinline__ void mma16816h(float* c,
    uint32_t a0, uint32_t a1, uint32_t a2, uint32_t a3,
    uint32_t b0, uint32_t b1)
{
    asm volatile(
        "mma.sync.aligned.m16n8k16.row.col.f32.f16.f16.f32 "
        "{%0,%1,%2,%3},{%4,%5,%6,%7},{%8,%9},{%0,%1,%2,%3};"
        : "+f"(c[0]), "+f"(c[1]), "+f"(c[2]), "+f"(c[3])
        : "r"(a0), "r"(a1), "r"(a2), "r"(a3), "r"(b0), "r"(b1));
}

__device__ __forceinline__ void ldsm4(uint32_t addr,
    uint32_t& r0, uint32_t& r1, uint32_t& r2, uint32_t& r3)
{
    asm volatile("ldmatrix.sync.aligned.m8n8.x4.shared.b16 {%0,%1,%2,%3}, [%4];"
        : "=r"(r0), "=r"(r1), "=r"(r2), "=r"(r3) : "r"(addr));
}

__device__ __forceinline__ void cpa16(uint32_t daddr, const void* src) {
    asm volatile("cp.async.cg.shared.global [%0], [%1], 16;" :: "r"(daddr), "l"(src));
}
#define CP_COMMIT asm volatile("cp.async.commit_group;")
#define CP_WAIT1  asm volatile("cp.async.wait_group 1;")
#define CP_WAIT0  asm volatile("cp.async.wait_group 0;")

// ---------------- GEMM: C[M,N] = alpha * A[M,K] * B[N,K]^T ----------------
// fp32 staged via cp.async double-buffer; cvt to tf32 at fragment load (same
// rna rounding as before). Dynamic smem: 2 bufs x (A 4608 + B 4608 floats).
#define GEMM_SMEM 73728
__global__ __launch_bounds__(256, 2) void gemm_tf32_nt(
    const float* __restrict__ A, const float* __restrict__ Bm,
    float* __restrict__ C, int M, int N, int K, float alpha)
{
    extern __shared__ float gsm[];
    const uint32_t sbase = (uint32_t)__cvta_generic_to_shared(gsm);

    const int tid  = threadIdx.x;
    const int lane = tid & 31;
    const int wid  = tid >> 5;
    const int gid  = lane >> 2;
    const int tig  = lane & 3;
    const int wm   = (wid & 1) * 64;
    const int wn   = (wid >> 1) * 32;
    const int bm   = blockIdx.y * 128;
    const int bn   = blockIdx.x * 128;

    float acc[4][4][4];
#pragma unroll
    for (int i = 0; i < 4; i++)
#pragma unroll
        for (int j = 0; j < 4; j++)
#pragma unroll
            for (int r = 0; r < 4; r++) acc[i][j][r] = 0.f;

    auto issue = [&](int kt, int sel) {
        uint32_t base = sbase + (uint32_t)sel * 36864u;
#pragma unroll
        for (int it = 0; it < 4; it++) {
            int f4 = tid + it * 256;       // 0..1023
            int r  = f4 >> 3;              // 0..127
            int c  = (f4 & 7) << 2;        // 0..28
            uint32_t so = (uint32_t)(r * 36 + c) * 4;
            cpa16(base + so,           A  + (size_t)(bm + r) * K + kt + c);
            cpa16(base + 18432u + so,  Bm + (size_t)(bn + r) * K + kt + c);
        }
        CP_COMMIT;
    };

    issue(0, 0);

    for (int it = 0; it < 32; it++) {
        const int cur = it & 1;
        if (it < 31) issue((it + 1) * 32, cur ^ 1);
        if (it < 31) { CP_WAIT1; } else { CP_WAIT0; }
        __syncthreads();

        const float* Ab = gsm + cur * 9216;
        const float* Bb = Ab + 4608;
#pragma unroll
        for (int ks = 0; ks < 32; ks += 8) {
            uint32_t af[4][4], bf[4][2];
#pragma unroll
            for (int mt = 0; mt < 4; mt++) {
                const float* p = &Ab[(wm + mt * 16 + gid) * 36 + ks + tig];
                af[mt][0] = f2tf(p[0]);
                af[mt][1] = f2tf(p[8 * 36]);
                af[mt][2] = f2tf(p[4]);
                af[mt][3] = f2tf(p[8 * 36 + 4]);
            }
#pragma unroll
            for (int nt = 0; nt < 4; nt++) {
                const float* p = &Bb[(wn + nt * 8 + gid) * 36 + ks + tig];
                bf[nt][0] = f2tf(p[0]);
                bf[nt][1] = f2tf(p[4]);
            }
#pragma unroll
            for (int mt = 0; mt < 4; mt++)
#pragma unroll
                for (int nt = 0; nt < 4; nt++)
                    asm volatile(
                        "mma.sync.aligned.m16n8k8.row.col.f32.tf32.tf32.f32 "
                        "{%0,%1,%2,%3},{%4,%5,%6,%7},{%8,%9},{%0,%1,%2,%3};"
                        : "+f"(acc[mt][nt][0]), "+f"(acc[mt][nt][1]),
                          "+f"(acc[mt][nt][2]), "+f"(acc[mt][nt][3])
                        : "r"(af[mt][0]), "r"(af[mt][1]), "r"(af[mt][2]), "r"(af[mt][3]),
                          "r"(bf[nt][0]), "r"(bf[nt][1]));
        }
        __syncthreads();
    }

#pragma unroll
    for (int mt = 0; mt < 4; mt++) {
#pragma unroll
        for (int nt = 0; nt < 4; nt++) {
            int r0 = bm + wm + mt * 16 + gid;
            int c0 = bn + wn + nt * 8 + tig * 2;
            float2 v01 = make_float2(acc[mt][nt][0] * alpha, acc[mt][nt][1] * alpha);
            float2 v23 = make_float2(acc[mt][nt][2] * alpha, acc[mt][nt][3] * alpha);
            *reinterpret_cast<float2*>(C + (size_t)r0 * N + c0)       = v01;
            *reinterpret_cast<float2*>(C + (size_t)(r0 + 8) * N + c0) = v23;
        }
    }
}

// ---------------- RoPE on Q (in place), fp32 math ----------------
__global__ __launch_bounds__(256) void rope_q_kernel()
{
    int idx = blockIdx.x * blockDim.x + threadIdx.x;
    int i    = idx & 31;
    int head = (idx >> 5) & (NHH - 1);
    int row  = idx >> 9;
    int t    = row & (TT - 1);
    float* p = g_Q + (size_t)row * HHC + head * HDD + i;
    float x1 = p[0], x2 = p[32];
    float invf = exp2f(NLOG2F_STEP * (float)i);
    float arg = (float)t * invf;
    float s, c; sincosf(arg, &s, &c);
    p[0]  = x1 * c - x2 * s;
    p[32] = x2 * c + x1 * s;
}

// ---------------- Gather K + RoPE, write fp16 hi/lo [B,S,H] ----------------
__global__ __launch_bounds__(256) void gather_k_kernel(const int* __restrict__ outcell)
{
    int idx = blockIdx.x * blockDim.x + threadIdx.x;
    int i    = idx & 31;
    int head = (idx >> 5) & (NHH - 1);
    int rest = idx >> 9;
    int s    = rest % SSQ;
    int b    = rest / SSQ;
    int src  = (s < TT) ? s : outcell[b * EE + (s - TT)];

    size_t soff = (size_t)(b * TT + src) * HHC + head * HDD + i;
    size_t doff = (size_t)(b * SSQ + s) * HHC + head * HDD + i;

    float k1 = g_K[soff], k2 = g_K[soff + 32];
    float invf = exp2f(NLOG2F_STEP * (float)i);
    float arg = (float)s * invf;
    float sn, cs; sincosf(arg, &sn, &cs);
    float r1 = k1 * cs - k2 * sn;
    float r2 = k2 * cs + k1 * sn;
    __half hh, ll;
    hsplit(r1, hh, ll); g_Khi[doff]      = hh; g_Klo[doff]      = ll;
    hsplit(r2, hh, ll); g_Khi[doff + 32] = hh; g_Klo[doff + 32] = ll;
}

// ---------------- Gather V transposed via smem (coalesced both sides) ----------------
// grid (SSQ/64, B*NH), 256 threads. Tile: 64 s x 64 d.
__global__ __launch_bounds__(256) void gather_vt_kernel(const int* __restrict__ outcell)
{
    __shared__ float ts[64][65];
    const int tid = threadIdx.x;
    const int s0  = blockIdx.x * 64;
    const int bh  = blockIdx.y;
    const int b   = bh >> 4, h = bh & (NHH - 1);

#pragma unroll
    for (int it = 0; it < 16; it++) {
        int sl = it * 4 + (tid >> 6);
        int d  = tid & 63;
        int s  = s0 + sl;
        int src = (s < TT) ? s : outcell[b * EE + (s - TT)];
        ts[d][sl] = g_V[(size_t)(b * TT + src) * HHC + h * HDD + d];
    }
    __syncthreads();

    int d  = tid >> 2;
    int sq = (tid & 3) * 16;
    uint32_t phi[8], plo[8];
#pragma unroll
    for (int j = 0; j < 8; j++) {
        __half h0, l0, h1, l1;
        hsplit(ts[d][sq + 2*j],     h0, l0);
        hsplit(ts[d][sq + 2*j + 1], h1, l1);
        __half2 th(h0, h1), tl(l0, l1);
        phi[j] = *(uint32_t*)&th;
        plo[j] = *(uint32_t*)&tl;
    }
    size_t o = (size_t)(bh * HDD + d) * SSQ + s0 + sq;
    *(uint4*)(g_Vthi + o)     = make_uint4(phi[0], phi[1], phi[2], phi[3]);
    *(uint4*)(g_Vthi + o + 8) = make_uint4(phi[4], phi[5], phi[6], phi[7]);
    *(uint4*)(g_Vtlo + o)     = make_uint4(plo[0], plo[1], plo[2], plo[3]);
    *(uint4*)(g_Vtlo + o + 8) = make_uint4(plo[4], plo[5], plo[6], plo[7]);
}

// ---------------- Attention: flash, fp16 2-pass mma, cp.async double-buffer ----------------
// SMEM layout (bytes):
//   Qh   [128][72] @ 0      (18432)
//   buf{0,1} @ 18432 + sel*36864, each:
//     Khi [64][72] +0, Klo +9216, Vthi +18432, Vtlo +27648  (9216 each)
//   maskS (64 floats) @ 92160
#define ATT_SMEM 92416
__global__ __launch_bounds__(256, 2) void attn_mma_kernel(
    const float* __restrict__ bias, const float* __restrict__ lw,
    const unsigned char* __restrict__ keypad, const unsigned char* __restrict__ expand)
{
    extern __shared__ char smraw[];
    __half* Qh = (__half*)smraw;
    float* maskS = (float*)(smraw + 92160);
    const uint32_t sbase = (uint32_t)__cvta_generic_to_shared(smraw);

    const int tid  = threadIdx.x;
    const int lane = tid & 31;
    const int w    = tid >> 5;
    const int gid  = lane >> 2;
    const int tig  = lane & 3;
    const int h = blockIdx.y, b = blockIdx.z;
    const int bh = b * NHH + h;
    const int q0 = blockIdx.x * 128;
    const int qw = w * 16;

    const __half* gKhi  = g_Khi  + (size_t)b * SSQ * HHC + h * HDD;
    const __half* gKlo  = g_Klo  + (size_t)b * SSQ * HHC + h * HDD;
    const __half* gVthi = g_Vthi + (size_t)bh * HDD * SSQ;
    const __half* gVtlo = g_Vtlo + (size_t)bh * HDD * SSQ;

    auto issue_tile = [&](int kc, int sel) {
        uint32_t bbase = sbase + 18432u + (uint32_t)sel * 36864u;
#pragma unroll
        for (int half_ = 0; half_ < 2; half_++) {
            int chunk = tid + half_ * 256;      // 0..511
            int row = chunk >> 3;               // 0..63
            int ce  = (chunk & 7) * 8;          // fp16 offset 0..56
            uint32_t so = (uint32_t)(row * 72 + ce) * 2;
            cpa16(bbase + so,          gKhi  + (size_t)(kc + row) * HHC + ce);
            cpa16(bbase + 9216u + so,  gKlo  + (size_t)(kc + row) * HHC + ce);
            cpa16(bbase + 18432u + so, gVthi + (size_t)row * SSQ + kc + ce);
            cpa16(bbase + 27648u + so, gVtlo + (size_t)row * SSQ + kc + ce);
        }
        CP_COMMIT;
    };

    issue_tile(0, 0);

    // ---- stage Q (fp16 hi only; q_lo error absorbed by split K) ----
#pragma unroll
    for (int it = 0; it < 8; it++) {
        int f4 = tid + it * 256;
        int r  = f4 >> 4;
        int c  = (f4 & 15) * 4;
        float4 v = *(const float4*)(g_Q + (size_t)(b * TT + q0 + r) * HHC + h * HDD + c);
        Qh[r*72+c+0] = __float2half_rn(v.x);
        Qh[r*72+c+1] = __float2half_rn(v.y);
        Qh[r*72+c+2] = __float2half_rn(v.z);
        Qh[r*72+c+3] = __float2half_rn(v.w);
    }
    __syncthreads();

    // ---- Q fragments (resident) ----
    uint32_t qh[4][4];
#pragma unroll
    for (int ks = 0; ks < 4; ks++) {
        int c0 = 2 * tig + 16 * ks;
        qh[ks][0] = *(uint32_t*)&Qh[(qw + gid)     * 72 + c0];
        qh[ks][1] = *(uint32_t*)&Qh[(qw + gid + 8) * 72 + c0];
        qh[ks][2] = *(uint32_t*)&Qh[(qw + gid)     * 72 + c0 + 8];
        qh[ks][3] = *(uint32_t*)&Qh[(qw + gid + 8) * 72 + c0 + 8];
    }

    float m0 = -INFINITY, m1 = -INFINITY, l0 = 0.f, l1 = 0.f;
    float pacc[8][4];
#pragma unroll
    for (int nt = 0; nt < 8; nt++)
#pragma unroll
        for (int c = 0; c < 4; c++) pacc[nt][c] = 0.f;

    const float* biasB = bias + ((size_t)(b * NHH + h) * TT + q0) * SSQ;
    const float* lwB   = lw   + ((size_t)b * TT + q0) * SSQ;

    const uint32_t lanoff =
        (uint32_t)((((lane >> 4) & 1) * 8 + (lane & 7)) * 72 + ((lane >> 3) & 1) * 8) * 2;

    for (int i = 0; i < 24; i++) {
        const int kc = i * 64;
        const int cur = i & 1;
        if (i < 23) issue_tile(kc + 64, cur ^ 1);
        if (i < 23) { CP_WAIT1; } else { CP_WAIT0; }
        if (tid < 64) {
            int s = kc + tid;
            unsigned char mk = (s < TT) ? keypad[b * TT + s] : expand[b * EE + (s - TT)];
            maskS[tid] = mk ? 1.f : 0.f;
        }
        __syncthreads();

        const uint32_t kbHi = sbase + 18432u + (uint32_t)cur * 36864u;
        const uint32_t kbLo = kbHi + 9216u;
        const uint32_t vbHi = kbHi + 18432u;
        const uint32_t vbLo = kbHi + 27648u;

        // ---- QK^T: q_hi x (k_hi + k_lo), 2-pass ----
        float sacc[8][4];
#pragma unroll
        for (int nt = 0; nt < 8; nt++)
#pragma unroll
            for (int c = 0; c < 4; c++) sacc[nt][c] = 0.f;

#pragma unroll
        for (int ks = 0; ks < 4; ks++) {
#pragma unroll
            for (int p = 0; p < 4; p++) {
                uint32_t off = lanoff + (uint32_t)(p * 2304 + ks * 32);
                uint32_t bh0, bh1, bh2, bh3, bl0, bl1, bl2, bl3;
                ldsm4(kbHi + off, bh0, bh1, bh2, bh3);
                ldsm4(kbLo + off, bl0, bl1, bl2, bl3);
                mma16816h(sacc[2*p],   qh[ks][0], qh[ks][1], qh[ks][2], qh[ks][3], bh0, bh1);
                mma16816h(sacc[2*p],   qh[ks][0], qh[ks][1], qh[ks][2], qh[ks][3], bl0, bl1);
                mma16816h(sacc[2*p+1], qh[ks][0], qh[ks][1], qh[ks][2], qh[ks][3], bh2, bh3);
                mma16816h(sacc[2*p+1], qh[ks][0], qh[ks][1], qh[ks][2], qh[ks][3], bl2, bl3);
            }
        }

        // ---- pass 1: + bias, masks, row max ----
        float rmax0 = -INFINITY, rmax1 = -INFINITY;
#pragma unroll
        for (int nt = 0; nt < 8; nt++) {
            int col = kc + 8 * nt + 2 * tig;
            float2 bb0 = __ldg((const float2*)(biasB + (size_t)(qw + gid)     * SSQ + col));
            float2 bb1 = __ldg((const float2*)(biasB + (size_t)(qw + gid + 8) * SSQ + col));
            float2 w0  = __ldg((const float2*)(lwB   + (size_t)(qw + gid)     * SSQ + col));
            float2 w1  = __ldg((const float2*)(lwB   + (size_t)(qw + gid + 8) * SSQ + col));
            float mk0 = maskS[8 * nt + 2 * tig];
            float mk1 = maskS[8 * nt + 2 * tig + 1];
            float v0 = sacc[nt][0] + bb0.x; if (mk0 != 0.f || w0.x <= 1e-5f) v0 = -INFINITY;
            float v1 = sacc[nt][1] + bb0.y; if (mk1 != 0.f || w0.y <= 1e-5f) v1 = -INFINITY;
            float v2 = sacc[nt][2] + bb1.x; if (mk0 != 0.f || w1.x <= 1e-5f) v2 = -INFINITY;
            float v3 = sacc[nt][3] + bb1.y; if (mk1 != 0.f || w1.y <= 1e-5f) v3 = -INFINITY;
            sacc[nt][0] = v0; sacc[nt][1] = v1; sacc[nt][2] = v2; sacc[nt][3] = v3;
            rmax0 = fmaxf(rmax0, fmaxf(v0, v1));
            rmax1 = fmaxf(rmax1, fmaxf(v2, v3));
        }
        rmax0 = fmaxf(rmax0, __shfl_xor_sync(0xffffffffu, rmax0, 1));
        rmax0 = fmaxf(rmax0, __shfl_xor_sync(0xffffffffu, rmax0, 2));
        rmax1 = fmaxf(rmax1, __shfl_xor_sync(0xffffffffu, rmax1, 1));
        rmax1 = fmaxf(rmax1, __shfl_xor_sync(0xffffffffu, rmax1, 2));

        float mn0 = fmaxf(m0, rmax0), mn1 = fmaxf(m1, rmax1);
        float sc0 = (mn0 == -INFINITY) ? 1.f : __expf(m0 - mn0);
        float sc1 = (mn1 == -INFINITY) ? 1.f : __expf(m1 - mn1);
        m0 = mn0; m1 = mn1;

#pragma unroll
        for (int nt = 0; nt < 8; nt++) {
            pacc[nt][0] *= sc0; pacc[nt][1] *= sc0;
            pacc[nt][2] *= sc1; pacc[nt][3] *= sc1;
        }

        // ---- fused pass 2 + PV: p_hi x (v_hi + v_lo), 2-pass ----
        float ps0 = 0.f, ps1 = 0.f;
#pragma unroll
        for (int ks = 0; ks < 4; ks++) {
            uint32_t ah[4];
#pragma unroll
            for (int j = 0; j < 2; j++) {
                int nt = 2 * ks + j;
                int col = kc + 8 * nt + 2 * tig;
                float2 w0 = __ldg((const float2*)(lwB + (size_t)(qw + gid)     * SSQ + col));
                float2 w1 = __ldg((const float2*)(lwB + (size_t)(qw + gid + 8) * SSQ + col));
                float e0 = (sacc[nt][0] == -INFINITY) ? 0.f : __expf(sacc[nt][0] - mn0);
                float e1 = (sacc[nt][1] == -INFINITY) ? 0.f : __expf(sacc[nt][1] - mn0);
                float e2 = (sacc[nt][2] == -INFINITY) ? 0.f : __expf(sacc[nt][2] - mn1);
                float e3 = (sacc[nt][3] == -INFINITY) ? 0.f : __expf(sacc[nt][3] - mn1);
                ps0 += e0 + e1; ps1 += e2 + e3;
                __half2 t0 = __floats2half2_rn(e0 * w0.x, e1 * w0.y);
                __half2 t1 = __floats2half2_rn(e2 * w1.x, e3 * w1.y);
                ah[2*j]     = *(uint32_t*)&t0;
                ah[2*j + 1] = *(uint32_t*)&t1;
            }
#pragma unroll
            for (int p = 0; p < 4; p++) {
                uint32_t off = lanoff + (uint32_t)(p * 2304 + ks * 32);
                uint32_t vh0, vh1, vh2, vh3, vl0, vl1, vl2, vl3;
                ldsm4(vbHi + off, vh0, vh1, vh2, vh3);
                ldsm4(vbLo + off, vl0, vl1, vl2, vl3);
                mma16816h(pacc[2*p],   ah[0], ah[1], ah[2], ah[3], vh0, vh1);
                mma16816h(pacc[2*p],   ah[0], ah[1], ah[2], ah[3], vl0, vl1);
                mma16816h(pacc[2*p+1], ah[0], ah[1], ah[2], ah[3], vh2, vh3);
                mma16816h(pacc[2*p+1], ah[0], ah[1], ah[2], ah[3], vl2, vl3);
            }
        }
        ps0 += __shfl_xor_sync(0xffffffffu, ps0, 1);
        ps0 += __shfl_xor_sync(0xffffffffu, ps0, 2);
        ps1 += __shfl_xor_sync(0xffffffffu, ps1, 1);
        ps1 += __shfl_xor_sync(0xffffffffu, ps1, 2);
        l0 = l0 * sc0 + ps0;
        l1 = l1 * sc1 + ps1;
        __syncthreads();
    }

    // ---- epilogue ----
    float inv0 = 1.f / l0, inv1 = 1.f / l1;
#pragma unroll
    for (int nt = 0; nt < 8; nt++) {
        int d = 8 * nt + 2 * tig;
        size_t o0 = (size_t)(b * TT + q0 + qw + gid)     * HHC + h * HDD + d;
        size_t o1 = (size_t)(b * TT + q0 + qw + gid + 8) * HHC + h * HDD + d;
        *(float2*)(g_att + o0) = make_float2(pacc[nt][0] * inv0, pacc[nt][1] * inv0);
        *(float2*)(g_att + o1) = make_float2(pacc[nt][2] * inv1, pacc[nt][3] * inv1);
    }
}

// ---------------- LayerNorm over H=1024 ----------------
__global__ __launch_bounds__(256) void ln_kernel(
    const float* __restrict__ gam, const float* __restrict__ bet)
{
    __shared__ float red[2][32];
    int row = blockIdx.x;
    const float* x = g_att + (size_t)row * HHC;
    float v[4], s = 0.f, sq = 0.f;
#pragma unroll
    for (int i = 0; i < 4; i++) {
        v[i] = x[threadIdx.x + i * 256];
        s += v[i]; sq += v[i] * v[i];
    }
#pragma unroll
    for (int o = 16; o; o >>= 1) {
        s  += __shfl_xor_sync(0xffffffffu, s,  o);
        sq += __shfl_xor_sync(0xffffffffu, sq, o);
    }
    int lane = threadIdx.x & 31, w = threadIdx.x >> 5;
    if (lane == 0) { red[0][w] = s; red[1][w] = sq; }
    __syncthreads();
    if (w == 0) {
        s  = (lane < 8) ? red[0][lane] : 0.f;
        sq = (lane < 8) ? red[1][lane] : 0.f;
#pragma unroll
        for (int o = 4; o; o >>= 1) {
            s  += __shfl_xor_sync(0xffffffffu, s,  o);
            sq += __shfl_xor_sync(0xffffffffu, sq, o);
        }
        if (lane == 0) { red[0][0] = s; red[1][0] = sq; }
    }
    __syncthreads();
    float mu  = red[0][0] * (1.f / HHC);
    float var = red[1][0] * (1.f / HHC) - mu * mu;
    float rs  = rsqrtf(var + LN_EPS);
#pragma unroll
    for (int i = 0; i < 4; i++) {
        int c = threadIdx.x + i * 256;
        g_ln[(size_t)row * HHC + c] = (v[i] - mu) * rs * gam[c] + bet[c];
    }
}

// ---------------- launch ----------------
extern "C" void kernel_launch(void* const* d_in, const int* in_sizes, int n_in,
                              void* d_out, int out_size)
{
    const float* x    = (const float*)d_in[0];
    const float* bias = (const float*)d_in[1];
    const float* lw   = (const float*)d_in[2];
    const unsigned char* kpm = (const unsigned char*)d_in[3];
    const int*   outcell = (const int*)d_in[4];
    const unsigned char* epm = (const unsigned char*)d_in[5];
    const float* wq  = (const float*)d_in[6];
    const float* wk  = (const float*)d_in[7];
    const float* wv  = (const float*)d_in[8];
    const float* wo  = (const float*)d_in[9];
    const float* lng = (const float*)d_in[10];
    const float* lnb = (const float*)d_in[11];
    float* out = (float*)d_out;

    float *Q, *K, *V, *LN;
    cudaGetSymbolAddress((void**)&Q,  g_Q);
    cudaGetSymbolAddress((void**)&K,  g_K);
    cudaGetSymbolAddress((void**)&V,  g_V);
    cudaGetSymbolAddress((void**)&LN, g_ln);

    cudaFuncSetAttribute(gemm_tf32_nt, cudaFuncAttributeMaxDynamicSharedMemorySize, GEMM_SMEM);
    cudaFuncSetAttribute(attn_mma_kernel, cudaFuncAttributeMaxDynamicSharedMemorySize, ATT_SMEM);

    dim3 gg(HHC / 128, (BB * TT) / 128);
    gemm_tf32_nt<<<gg, 256, GEMM_SMEM>>>(x, wq, Q, BB * TT, HHC, HHC, SCALING);
    gemm_tf32_nt<<<gg, 256, GEMM_SMEM>>>(x, wk, K, BB * TT, HHC, HHC, 1.f);
    gemm_tf32_nt<<<gg, 256, GEMM_SMEM>>>(x, wv, V, BB * TT, HHC, HHC, 1.f);

    rope_q_kernel<<<(BB * TT * NHH * 32) / 256, 256>>>();
    gather_k_kernel<<<(BB * SSQ * NHH * 32) / 256, 256>>>(outcell);
    gather_vt_kernel<<<dim3(SSQ / 64, BB * NHH), 256>>>(outcell);

    attn_mma_kernel<<<dim3(TT / 128, NHH, BB), 256, ATT_SMEM>>>(bias, lw, kpm, epm);

    ln_kernel<<<BB * TT, 256>>>(lng, lnb);

    gemm_tf32_nt<<<gg, 256, GEMM_SMEM>>>(LN, wo, out, BB * TT, HHC, HHC, 1.f);
}

// round 13
// speedup vs baseline: 1.7860x; 1.1286x over previous
#include <cuda_runtime.h>
#include <cuda_fp16.h>
#include <cstdint>

// Problem constants
#define BB   4
#define TT   1024
#define EE   512
#define SSQ  1536   // S = T + E
#define HHC  1024   // hidden
#define NHH  16
#define HDD  64
#define LN_EPS 1e-5f
#define SCALING 0.125f   // sqrt(64)/64

// -log2(10000)/32
#define NLOG2F_STEP (-0.4152410118609203f)

// ---------------- scratch ----------------
__device__ float g_Q  [BB*TT*HHC];    // rope'd Q, [B,T,H]
__device__ float g_K  [BB*TT*HHC];    // raw K projection
__device__ float g_V  [BB*TT*HHC];    // raw V projection
__device__ float g_att[BB*TT*HHC];    // attention out pre-LN
__device__ float g_ln [BB*TT*HHC];    // LN output
// fp16 K (gathered+rope'd), [B,S,H]
__device__ __half g_Kh[BB*SSQ*HHC];
// fp16 V, transposed per head: [B*NH, HD, S]
__device__ __half g_Vth[BB*NHH*HDD*SSQ];

// ---------------- helpers ----------------
__device__ __forceinline__ uint32_t f2tf(float f) {
    uint32_t u; asm("cvt.rna.tf32.f32 %0, %1;" : "=r"(u) : "f"(f)); return u;
}

__device__ __forceinline__ void mma16816h(float* c,
    uint32_t a0, uint32_t a1, uint32_t a2, uint32_t a3,
    uint32_t b0, uint32_t b1)
{
    asm volatile(
        "mma.sync.aligned.m16n8k16.row.col.f32.f16.f16.f32 "
        "{%0,%1,%2,%3},{%4,%5,%6,%7},{%8,%9},{%0,%1,%2,%3};"
        : "+f"(c[0]), "+f"(c[1]), "+f"(c[2]), "+f"(c[3])
        : "r"(a0), "r"(a1), "r"(a2), "r"(a3), "r"(b0), "r"(b1));
}

__device__ __forceinline__ void ldsm4(uint32_t addr,
    uint32_t& r0, uint32_t& r1, uint32_t& r2, uint32_t& r3)
{
    asm volatile("ldmatrix.sync.aligned.m8n8.x4.shared.b16 {%0,%1,%2,%3}, [%4];"
        : "=r"(r0), "=r"(r1), "=r"(r2), "=r"(r3) : "r"(addr));
}

__device__ __forceinline__ void cpa16(uint32_t daddr, const void* src) {
    asm volatile("cp.async.cg.shared.global [%0], [%1], 16;" :: "r"(daddr), "l"(src));
}
#define CP_COMMIT asm volatile("cp.async.commit_group;")
#define CP_WAIT1  asm volatile("cp.async.wait_group 1;")
#define CP_WAIT0  asm volatile("cp.async.wait_group 0;")

// ---------------- GEMM: C[M,N] = alpha * A[M,K] * B[N,K]^T ----------------
#define GEMM_SMEM 73728
__global__ __launch_bounds__(256, 2) void gemm_tf32_nt(
    const float* __restrict__ A, const float* __restrict__ Bm,
    float* __restrict__ C, int M, int N, int K, float alpha)
{
    extern __shared__ float gsm[];
    const uint32_t sbase = (uint32_t)__cvta_generic_to_shared(gsm);

    const int tid  = threadIdx.x;
    const int lane = tid & 31;
    const int wid  = tid >> 5;
    const int gid  = lane >> 2;
    const int tig  = lane & 3;
    const int wm   = (wid & 1) * 64;
    const int wn   = (wid >> 1) * 32;
    const int bm   = blockIdx.y * 128;
    const int bn   = blockIdx.x * 128;

    float acc[4][4][4];
#pragma unroll
    for (int i = 0; i < 4; i++)
#pragma unroll
        for (int j = 0; j < 4; j++)
#pragma unroll
            for (int r = 0; r < 4; r++) acc[i][j][r] = 0.f;

    auto issue = [&](int kt, int sel) {
        uint32_t base = sbase + (uint32_t)sel * 36864u;
#pragma unroll
        for (int it = 0; it < 4; it++) {
            int f4 = tid + it * 256;
            int r  = f4 >> 3;
            int c  = (f4 & 7) << 2;
            uint32_t so = (uint32_t)(r * 36 + c) * 4;
            cpa16(base + so,           A  + (size_t)(bm + r) * K + kt + c);
            cpa16(base + 18432u + so,  Bm + (size_t)(bn + r) * K + kt + c);
        }
        CP_COMMIT;
    };

    issue(0, 0);

    for (int it = 0; it < 32; it++) {
        const int cur = it & 1;
        if (it < 31) issue((it + 1) * 32, cur ^ 1);
        if (it < 31) { CP_WAIT1; } else { CP_WAIT0; }
        __syncthreads();

        const float* Ab = gsm + cur * 9216;
        const float* Bb = Ab + 4608;
#pragma unroll
        for (int ks = 0; ks < 32; ks += 8) {
            uint32_t af[4][4], bf[4][2];
#pragma unroll
            for (int mt = 0; mt < 4; mt++) {
                const float* p = &Ab[(wm + mt * 16 + gid) * 36 + ks + tig];
                af[mt][0] = f2tf(p[0]);
                af[mt][1] = f2tf(p[8 * 36]);
                af[mt][2] = f2tf(p[4]);
                af[mt][3] = f2tf(p[8 * 36 + 4]);
            }
#pragma unroll
            for (int nt = 0; nt < 4; nt++) {
                const float* p = &Bb[(wn + nt * 8 + gid) * 36 + ks + tig];
                bf[nt][0] = f2tf(p[0]);
                bf[nt][1] = f2tf(p[4]);
            }
#pragma unroll
            for (int mt = 0; mt < 4; mt++)
#pragma unroll
                for (int nt = 0; nt < 4; nt++)
                    asm volatile(
                        "mma.sync.aligned.m16n8k8.row.col.f32.tf32.tf32.f32 "
                        "{%0,%1,%2,%3},{%4,%5,%6,%7},{%8,%9},{%0,%1,%2,%3};"
                        : "+f"(acc[mt][nt][0]), "+f"(acc[mt][nt][1]),
                          "+f"(acc[mt][nt][2]), "+f"(acc[mt][nt][3])
                        : "r"(af[mt][0]), "r"(af[mt][1]), "r"(af[mt][2]), "r"(af[mt][3]),
                          "r"(bf[nt][0]), "r"(bf[nt][1]));
        }
        __syncthreads();
    }

#pragma unroll
    for (int mt = 0; mt < 4; mt++) {
#pragma unroll
        for (int nt = 0; nt < 4; nt++) {
            int r0 = bm + wm + mt * 16 + gid;
            int c0 = bn + wn + nt * 8 + tig * 2;
            float2 v01 = make_float2(acc[mt][nt][0] * alpha, acc[mt][nt][1] * alpha);
            float2 v23 = make_float2(acc[mt][nt][2] * alpha, acc[mt][nt][3] * alpha);
            *reinterpret_cast<float2*>(C + (size_t)r0 * N + c0)       = v01;
            *reinterpret_cast<float2*>(C + (size_t)(r0 + 8) * N + c0) = v23;
        }
    }
}

// ---------------- RoPE on Q (in place), fp32 math ----------------
__global__ __launch_bounds__(256) void rope_q_kernel()
{
    int idx = blockIdx.x * blockDim.x + threadIdx.x;
    int i    = idx & 31;
    int head = (idx >> 5) & (NHH - 1);
    int row  = idx >> 9;
    int t    = row & (TT - 1);
    float* p = g_Q + (size_t)row * HHC + head * HDD + i;
    float x1 = p[0], x2 = p[32];
    float invf = exp2f(NLOG2F_STEP * (float)i);
    float arg = (float)t * invf;
    float s, c; sincosf(arg, &s, &c);
    p[0]  = x1 * c - x2 * s;
    p[32] = x2 * c + x1 * s;
}

// ---------------- Gather K + RoPE, write fp16 [B,S,H] ----------------
__global__ __launch_bounds__(256) void gather_k_kernel(const int* __restrict__ outcell)
{
    int idx = blockIdx.x * blockDim.x + threadIdx.x;
    int i    = idx & 31;
    int head = (idx >> 5) & (NHH - 1);
    int rest = idx >> 9;
    int s    = rest % SSQ;
    int b    = rest / SSQ;
    int src  = (s < TT) ? s : outcell[b * EE + (s - TT)];

    size_t soff = (size_t)(b * TT + src) * HHC + head * HDD + i;
    size_t doff = (size_t)(b * SSQ + s) * HHC + head * HDD + i;

    float k1 = g_K[soff], k2 = g_K[soff + 32];
    float invf = exp2f(NLOG2F_STEP * (float)i);
    float arg = (float)s * invf;
    float sn, cs; sincosf(arg, &sn, &cs);
    g_Kh[doff]      = __float2half_rn(k1 * cs - k2 * sn);
    g_Kh[doff + 32] = __float2half_rn(k2 * cs + k1 * sn);
}

// ---------------- Gather V transposed via smem (coalesced both sides) ----------------
// grid (SSQ/64, B*NH), 256 threads. Tile: 64 s x 64 d.
__global__ __launch_bounds__(256) void gather_vt_kernel(const int* __restrict__ outcell)
{
    __shared__ float ts[64][65];
    const int tid = threadIdx.x;
    const int s0  = blockIdx.x * 64;
    const int bh  = blockIdx.y;
    const int b   = bh >> 4, h = bh & (NHH - 1);

#pragma unroll
    for (int it = 0; it < 16; it++) {
        int sl = it * 4 + (tid >> 6);
        int d  = tid & 63;
        int s  = s0 + sl;
        int src = (s < TT) ? s : outcell[b * EE + (s - TT)];
        ts[d][sl] = g_V[(size_t)(b * TT + src) * HHC + h * HDD + d];
    }
    __syncthreads();

    int d  = tid >> 2;
    int sq = (tid & 3) * 16;
    uint32_t ph[8];
#pragma unroll
    for (int j = 0; j < 8; j++) {
        __half2 t = __floats2half2_rn(ts[d][sq + 2*j], ts[d][sq + 2*j + 1]);
        ph[j] = *(uint32_t*)&t;
    }
    size_t o = (size_t)(bh * HDD + d) * SSQ + s0 + sq;
    *(uint4*)(g_Vth + o)     = make_uint4(ph[0], ph[1], ph[2], ph[3]);
    *(uint4*)(g_Vth + o + 8) = make_uint4(ph[4], ph[5], ph[6], ph[7]);
}

// ---------------- Attention: flash, pure fp16 mma (fp32 accum), cp.async DB ----------------
// SMEM layout (bytes):
//   Qh   [128][72] @ 0      (18432)
//   buf{0,1} @ 18432 + sel*18432, each: Kh [64][72] +0, Vth [64][72] +9216
//   maskS (64 floats) @ 55296
#define ATT_SMEM 55552
__global__ __launch_bounds__(256, 2) void attn_mma_kernel(
    const float* __restrict__ bias, const float* __restrict__ lw,
    const unsigned char* __restrict__ keypad, const unsigned char* __restrict__ expand)
{
    extern __shared__ char smraw[];
    __half* Qh = (__half*)smraw;
    float* maskS = (float*)(smraw + 55296);
    const uint32_t sbase = (uint32_t)__cvta_generic_to_shared(smraw);

    const int tid  = threadIdx.x;
    const int lane = tid & 31;
    const int w    = tid >> 5;
    const int gid  = lane >> 2;
    const int tig  = lane & 3;
    const int h = blockIdx.y, b = blockIdx.z;
    const int bh = b * NHH + h;
    const int q0 = blockIdx.x * 128;
    const int qw = w * 16;

    const __half* gKh  = g_Kh  + (size_t)b * SSQ * HHC + h * HDD;
    const __half* gVth = g_Vth + (size_t)bh * HDD * SSQ;

    auto issue_tile = [&](int kc, int sel) {
        uint32_t bbase = sbase + 18432u + (uint32_t)sel * 18432u;
#pragma unroll
        for (int half_ = 0; half_ < 2; half_++) {
            int chunk = tid + half_ * 256;      // 0..511
            int row = chunk >> 3;               // 0..63
            int ce  = (chunk & 7) * 8;          // fp16 offset 0..56
            uint32_t so = (uint32_t)(row * 72 + ce) * 2;
            cpa16(bbase + so,         gKh  + (size_t)(kc + row) * HHC + ce);
            cpa16(bbase + 9216u + so, gVth + (size_t)row * SSQ + kc + ce);
        }
        CP_COMMIT;
    };

    issue_tile(0, 0);

    // ---- stage Q (fp16) ----
#pragma unroll
    for (int it = 0; it < 8; it++) {
        int f4 = tid + it * 256;
        int r  = f4 >> 4;
        int c  = (f4 & 15) * 4;
        float4 v = *(const float4*)(g_Q + (size_t)(b * TT + q0 + r) * HHC + h * HDD + c);
        Qh[r*72+c+0] = __float2half_rn(v.x);
        Qh[r*72+c+1] = __float2half_rn(v.y);
        Qh[r*72+c+2] = __float2half_rn(v.z);
        Qh[r*72+c+3] = __float2half_rn(v.w);
    }
    __syncthreads();

    // ---- Q fragments (resident) ----
    uint32_t qh[4][4];
#pragma unroll
    for (int ks = 0; ks < 4; ks++) {
        int c0 = 2 * tig + 16 * ks;
        qh[ks][0] = *(uint32_t*)&Qh[(qw + gid)     * 72 + c0];
        qh[ks][1] = *(uint32_t*)&Qh[(qw + gid + 8) * 72 + c0];
        qh[ks][2] = *(uint32_t*)&Qh[(qw + gid)     * 72 + c0 + 8];
        qh[ks][3] = *(uint32_t*)&Qh[(qw + gid + 8) * 72 + c0 + 8];
    }

    float m0 = -INFINITY, m1 = -INFINITY, l0 = 0.f, l1 = 0.f;
    float pacc[8][4];
#pragma unroll
    for (int nt = 0; nt < 8; nt++)
#pragma unroll
        for (int c = 0; c < 4; c++) pacc[nt][c] = 0.f;

    const float* biasB = bias + ((size_t)(b * NHH + h) * TT + q0) * SSQ;
    const float* lwB   = lw   + ((size_t)b * TT + q0) * SSQ;

    const uint32_t lanoff =
        (uint32_t)((((lane >> 4) & 1) * 8 + (lane & 7)) * 72 + ((lane >> 3) & 1) * 8) * 2;

    for (int i = 0; i < 24; i++) {
        const int kc = i * 64;
        const int cur = i & 1;
        if (i < 23) issue_tile(kc + 64, cur ^ 1);
        if (i < 23) { CP_WAIT1; } else { CP_WAIT0; }
        if (tid < 64) {
            int s = kc + tid;
            unsigned char mk = (s < TT) ? keypad[b * TT + s] : expand[b * EE + (s - TT)];
            maskS[tid] = mk ? 1.f : 0.f;
        }
        __syncthreads();

        const uint32_t kb = sbase + 18432u + (uint32_t)cur * 18432u;
        const uint32_t vb = kb + 9216u;

        // ---- QK^T (single-pass fp16) ----
        float sacc[8][4];
#pragma unroll
        for (int nt = 0; nt < 8; nt++)
#pragma unroll
            for (int c = 0; c < 4; c++) sacc[nt][c] = 0.f;

#pragma unroll
        for (int ks = 0; ks < 4; ks++) {
#pragma unroll
            for (int p = 0; p < 4; p++) {
                uint32_t off = lanoff + (uint32_t)(p * 2304 + ks * 32);
                uint32_t bh0, bh1, bh2, bh3;
                ldsm4(kb + off, bh0, bh1, bh2, bh3);
                mma16816h(sacc[2*p],   qh[ks][0], qh[ks][1], qh[ks][2], qh[ks][3], bh0, bh1);
                mma16816h(sacc[2*p+1], qh[ks][0], qh[ks][1], qh[ks][2], qh[ks][3], bh2, bh3);
            }
        }

        // ---- pass 1: + bias, masks, row max ----
        float rmax0 = -INFINITY, rmax1 = -INFINITY;
#pragma unroll
        for (int nt = 0; nt < 8; nt++) {
            int col = kc + 8 * nt + 2 * tig;
            float2 bb0 = __ldg((const float2*)(biasB + (size_t)(qw + gid)     * SSQ + col));
            float2 bb1 = __ldg((const float2*)(biasB + (size_t)(qw + gid + 8) * SSQ + col));
            float2 w0  = __ldg((const float2*)(lwB   + (size_t)(qw + gid)     * SSQ + col));
            float2 w1  = __ldg((const float2*)(lwB   + (size_t)(qw + gid + 8) * SSQ + col));
            float mk0 = maskS[8 * nt + 2 * tig];
            float mk1 = maskS[8 * nt + 2 * tig + 1];
            float v0 = sacc[nt][0] + bb0.x; if (mk0 != 0.f || w0.x <= 1e-5f) v0 = -INFINITY;
            float v1 = sacc[nt][1] + bb0.y; if (mk1 != 0.f || w0.y <= 1e-5f) v1 = -INFINITY;
            float v2 = sacc[nt][2] + bb1.x; if (mk0 != 0.f || w1.x <= 1e-5f) v2 = -INFINITY;
            float v3 = sacc[nt][3] + bb1.y; if (mk1 != 0.f || w1.y <= 1e-5f) v3 = -INFINITY;
            sacc[nt][0] = v0; sacc[nt][1] = v1; sacc[nt][2] = v2; sacc[nt][3] = v3;
            rmax0 = fmaxf(rmax0, fmaxf(v0, v1));
            rmax1 = fmaxf(rmax1, fmaxf(v2, v3));
        }
        rmax0 = fmaxf(rmax0, __shfl_xor_sync(0xffffffffu, rmax0, 1));
        rmax0 = fmaxf(rmax0, __shfl_xor_sync(0xffffffffu, rmax0, 2));
        rmax1 = fmaxf(rmax1, __shfl_xor_sync(0xffffffffu, rmax1, 1));
        rmax1 = fmaxf(rmax1, __shfl_xor_sync(0xffffffffu, rmax1, 2));

        float mn0 = fmaxf(m0, rmax0), mn1 = fmaxf(m1, rmax1);
        float sc0 = (mn0 == -INFINITY) ? 1.f : __expf(m0 - mn0);
        float sc1 = (mn1 == -INFINITY) ? 1.f : __expf(m1 - mn1);
        m0 = mn0; m1 = mn1;

#pragma unroll
        for (int nt = 0; nt < 8; nt++) {
            pacc[nt][0] *= sc0; pacc[nt][1] *= sc0;
            pacc[nt][2] *= sc1; pacc[nt][3] *= sc1;
        }

        // ---- fused pass 2 + PV (single-pass fp16) ----
        float ps0 = 0.f, ps1 = 0.f;
#pragma unroll
        for (int ks = 0; ks < 4; ks++) {
            uint32_t ah[4];
#pragma unroll
            for (int j = 0; j < 2; j++) {
                int nt = 2 * ks + j;
                int col = kc + 8 * nt + 2 * tig;
                float2 w0 = __ldg((const float2*)(lwB + (size_t)(qw + gid)     * SSQ + col));
                float2 w1 = __ldg((const float2*)(lwB + (size_t)(qw + gid + 8) * SSQ + col));
                float e0 = (sacc[nt][0] == -INFINITY) ? 0.f : __expf(sacc[nt][0] - mn0);
                float e1 = (sacc[nt][1] == -INFINITY) ? 0.f : __expf(sacc[nt][1] - mn0);
                float e2 = (sacc[nt][2] == -INFINITY) ? 0.f : __expf(sacc[nt][2] - mn1);
                float e3 = (sacc[nt][3] == -INFINITY) ? 0.f : __expf(sacc[nt][3] - mn1);
                ps0 += e0 + e1; ps1 += e2 + e3;
                __half2 t0 = __floats2half2_rn(e0 * w0.x, e1 * w0.y);
                __half2 t1 = __floats2half2_rn(e2 * w1.x, e3 * w1.y);
                ah[2*j]     = *(uint32_t*)&t0;
                ah[2*j + 1] = *(uint32_t*)&t1;
            }
#pragma unroll
            for (int p = 0; p < 4; p++) {
                uint32_t off = lanoff + (uint32_t)(p * 2304 + ks * 32);
                uint32_t vh0, vh1, vh2, vh3;
                ldsm4(vb + off, vh0, vh1, vh2, vh3);
                mma16816h(pacc[2*p],   ah[0], ah[1], ah[2], ah[3], vh0, vh1);
                mma16816h(pacc[2*p+1], ah[0], ah[1], ah[2], ah[3], vh2, vh3);
            }
        }
        ps0 += __shfl_xor_sync(0xffffffffu, ps0, 1);
        ps0 += __shfl_xor_sync(0xffffffffu, ps0, 2);
        ps1 += __shfl_xor_sync(0xffffffffu, ps1, 1);
        ps1 += __shfl_xor_sync(0xffffffffu, ps1, 2);
        l0 = l0 * sc0 + ps0;
        l1 = l1 * sc1 + ps1;
        __syncthreads();
    }

    // ---- epilogue ----
    float inv0 = 1.f / l0, inv1 = 1.f / l1;
#pragma unroll
    for (int nt = 0; nt < 8; nt++) {
        int d = 8 * nt + 2 * tig;
        size_t o0 = (size_t)(b * TT + q0 + qw + gid)     * HHC + h * HDD + d;
        size_t o1 = (size_t)(b * TT + q0 + qw + gid + 8) * HHC + h * HDD + d;
        *(float2*)(g_att + o0) = make_float2(pacc[nt][0] * inv0, pacc[nt][1] * inv0);
        *(float2*)(g_att + o1) = make_float2(pacc[nt][2] * inv1, pacc[nt][3] * inv1);
    }
}

// ---------------- LayerNorm over H=1024 ----------------
__global__ __launch_bounds__(256) void ln_kernel(
    const float* __restrict__ gam, const float* __restrict__ bet)
{
    __shared__ float red[2][32];
    int row = blockIdx.x;
    const float* x = g_att + (size_t)row * HHC;
    float v[4], s = 0.f, sq = 0.f;
#pragma unroll
    for (int i = 0; i < 4; i++) {
        v[i] = x[threadIdx.x + i * 256];
        s += v[i]; sq += v[i] * v[i];
    }
#pragma unroll
    for (int o = 16; o; o >>= 1) {
        s  += __shfl_xor_sync(0xffffffffu, s,  o);
        sq += __shfl_xor_sync(0xffffffffu, sq, o);
    }
    int lane = threadIdx.x & 31, w = threadIdx.x >> 5;
    if (lane == 0) { red[0][w] = s; red[1][w] = sq; }
    __syncthreads();
    if (w == 0) {
        s  = (lane < 8) ? red[0][lane] : 0.f;
        sq = (lane < 8) ? red[1][lane] : 0.f;
#pragma unroll
        for (int o = 4; o; o >>= 1) {
            s  += __shfl_xor_sync(0xffffffffu, s,  o);
            sq += __shfl_xor_sync(0xffffffffu, sq, o);
        }
        if (lane == 0) { red[0][0] = s; red[1][0] = sq; }
    }
    __syncthreads();
    float mu  = red[0][0] * (1.f / HHC);
    float var = red[1][0] * (1.f / HHC) - mu * mu;
    float rs  = rsqrtf(var + LN_EPS);
#pragma unroll
    for (int i = 0; i < 4; i++) {
        int c = threadIdx.x + i * 256;
        g_ln[(size_t)row * HHC + c] = (v[i] - mu) * rs * gam[c] + bet[c];
    }
}

// ---------------- launch ----------------
extern "C" void kernel_launch(void* const* d_in, const int* in_sizes, int n_in,
                              void* d_out, int out_size)
{
    const float* x    = (const float*)d_in[0];
    const float* bias = (const float*)d_in[1];
    const float* lw   = (const float*)d_in[2];
    const unsigned char* kpm = (const unsigned char*)d_in[3];
    const int*   outcell = (const int*)d_in[4];
    const unsigned char* epm = (const unsigned char*)d_in[5];
    const float* wq  = (const float*)d_in[6];
    const float* wk  = (const float*)d_in[7];
    const float* wv  = (const float*)d_in[8];
    const float* wo  = (const float*)d_in[9];
    const float* lng = (const float*)d_in[10];
    const float* lnb = (const float*)d_in[11];
    float* out = (float*)d_out;

    float *Q, *K, *V, *LN;
    cudaGetSymbolAddress((void**)&Q,  g_Q);
    cudaGetSymbolAddress((void**)&K,  g_K);
    cudaGetSymbolAddress((void**)&V,  g_V);
    cudaGetSymbolAddress((void**)&LN, g_ln);

    cudaFuncSetAttribute(gemm_tf32_nt, cudaFuncAttributeMaxDynamicSharedMemorySize, GEMM_SMEM);
    cudaFuncSetAttribute(attn_mma_kernel, cudaFuncAttributeMaxDynamicSharedMemorySize, ATT_SMEM);

    dim3 gg(HHC / 128, (BB * TT) / 128);
    gemm_tf32_nt<<<gg, 256, GEMM_SMEM>>>(x, wq, Q, BB * TT, HHC, HHC, SCALING);
    gemm_tf32_nt<<<gg, 256, GEMM_SMEM>>>(x, wk, K, BB * TT, HHC, HHC, 1.f);
    gemm_tf32_nt<<<gg, 256, GEMM_SMEM>>>(x, wv, V, BB * TT, HHC, HHC, 1.f);

    rope_q_kernel<<<(BB * TT * NHH * 32) / 256, 256>>>();
    gather_k_kernel<<<(BB * SSQ * NHH * 32) / 256, 256>>>(outcell);
    gather_vt_kernel<<<dim3(SSQ / 64, BB * NHH), 256>>>(outcell);

    attn_mma_kernel<<<dim3(TT / 128, NHH, BB), 256, ATT_SMEM>>>(bias, lw, kpm, epm);

    ln_kernel<<<BB * TT, 256>>>(lng, lnb);

    gemm_tf32_nt<<<gg, 256, GEMM_SMEM>>>(LN, wo, out, BB * TT, HHC, HHC, 1.f);
}

// round 16
// speedup vs baseline: 1.8671x; 1.0454x over previous
#include <cuda_runtime.h>
#include <cuda_fp16.h>
#include <cstdint>

// Problem constants
#define BB   4
#define TT   1024
#define EE   512
#define SSQ  1536   // S = T + E
#define HHC  1024   // hidden
#define NHH  16
#define HDD  64
#define LN_EPS 1e-5f
#define SCALING 0.125f   // sqrt(64)/64

// -log2(10000)/32
#define NLOG2F_STEP (-0.4152410118609203f)

// ---------------- scratch ----------------
__device__ float g_Q  [BB*TT*HHC];    // rope'd Q, [B,T,H]
__device__ float g_K  [BB*TT*HHC];    // raw K projection
__device__ float g_V  [BB*TT*HHC];    // raw V projection
__device__ float g_att[BB*TT*HHC];    // attention out pre-LN
// fp16 staging
__device__ __half g_Xh [BB*TT*HHC];      // fp16(x)
__device__ __half g_LNh[BB*TT*HHC];      // fp16(LN out)
__device__ __half g_Wh [4*HHC*HHC];      // weight hi  (q,k,v,o)
__device__ __half g_Wl [4*HHC*HHC];      // weight lo
// fp16 K (gathered+rope'd), [B,S,H]
__device__ __half g_Kh[BB*SSQ*HHC];
// fp16 V, transposed per head: [B*NH, HD, S]
__device__ __half g_Vth[BB*NHH*HDD*SSQ];

// ---------------- helpers ----------------
__device__ __forceinline__ void mma16816h(float* c,
    uint32_t a0, uint32_t a1, uint32_t a2, uint32_t a3,
    uint32_t b0, uint32_t b1)
{
    asm volatile(
        "mma.sync.aligned.m16n8k16.row.col.f32.f16.f16.f32 "
        "{%0,%1,%2,%3},{%4,%5,%6,%7},{%8,%9},{%0,%1,%2,%3};"
        : "+f"(c[0]), "+f"(c[1]), "+f"(c[2]), "+f"(c[3])
        : "r"(a0), "r"(a1), "r"(a2), "r"(a3), "r"(b0), "r"(b1));
}

__device__ __forceinline__ void ldsm4(uint32_t addr,
    uint32_t& r0, uint32_t& r1, uint32_t& r2, uint32_t& r3)
{
    asm volatile("ldmatrix.sync.aligned.m8n8.x4.shared.b16 {%0,%1,%2,%3}, [%4];"
        : "=r"(r0), "=r"(r1), "=r"(r2), "=r"(r3) : "r"(addr));
}

__device__ __forceinline__ void cpa16(uint32_t daddr, const void* src) {
    asm volatile("cp.async.cg.shared.global [%0], [%1], 16;" :: "r"(daddr), "l"(src));
}
#define CP_COMMIT asm volatile("cp.async.commit_group;")
#define CP_WAIT1  asm volatile("cp.async.wait_group 1;")
#define CP_WAIT0  asm volatile("cp.async.wait_group 0;")

// ---------------- prologue: split weights to fp16 hi/lo ----------------
__global__ __launch_bounds__(256) void split_w_kernel(
    const float* __restrict__ w0, const float* __restrict__ w1,
    const float* __restrict__ w2, const float* __restrict__ w3)
{
    int idx = blockIdx.x * 256 + threadIdx.x;      // 0 .. 4M-1
    int m = idx >> 20;
    const float* src = (m == 0) ? w0 : (m == 1) ? w1 : (m == 2) ? w2 : w3;
    float v = src[idx & ((HHC*HHC) - 1)];
    __half h = __float2half_rn(v);
    g_Wh[idx] = h;
    g_Wl[idx] = __float2half_rn(v - __half2float(h));
}

// ---------------- prologue: x -> fp16 ----------------
__global__ __launch_bounds__(256) void xh_kernel(const float* __restrict__ x)
{
    int idx = blockIdx.x * 256 + threadIdx.x;      // 0 .. 1M-1 (float4 units)
    float4 v = *(const float4*)(x + (size_t)idx * 4);
    __half2 a = __floats2half2_rn(v.x, v.y);
    __half2 b = __floats2half2_rn(v.z, v.w);
    *(uint2*)(g_Xh + (size_t)idx * 4) = make_uint2(*(uint32_t*)&a, *(uint32_t*)&b);
}

// ---------------- GEMM: C[M,N] = alpha * A[M,K] * (Bh+Bl)[N,K]^T ----------------
// A fp16 single, B fp16 hi+lo 2-pass. ldmatrix + mma, cp.async double-buffer.
// smem/stage: A[128][40] @0 (10240 B), Bh @10240, Bl @20480 (rows padded to 80 B).
#define GEMM_SMEM 61440
__global__ __launch_bounds__(256, 2) void gemm_fp16_nt(
    const __half* __restrict__ A, const __half* __restrict__ Bhp,
    const __half* __restrict__ Blp, float* __restrict__ C,
    int M, int N, int K, float alpha)
{
    extern __shared__ char gsm[];
    const uint32_t sbase = (uint32_t)__cvta_generic_to_shared(gsm);

    const int tid  = threadIdx.x;
    const int lane = tid & 31;
    const int wid  = tid >> 5;
    const int gid  = lane >> 2;
    const int tig  = lane & 3;
    const int wm   = (wid & 1) * 64;
    const int wn   = (wid >> 1) * 32;
    const int bm   = blockIdx.y * 128;
    const int bn   = blockIdx.x * 128;

    const uint32_t lanoffA =
        (uint32_t)((lane & 15) * 80 + (lane >> 4) * 16);
    const uint32_t lanoffB =
        (uint32_t)((((lane >> 4) & 1) * 8 + (lane & 7)) * 80 + ((lane >> 3) & 1) * 16);

    float acc[4][4][4];
#pragma unroll
    for (int i = 0; i < 4; i++)
#pragma unroll
        for (int j = 0; j < 4; j++)
#pragma unroll
            for (int r = 0; r < 4; r++) acc[i][j][r] = 0.f;

    auto issue = [&](int kt, int sel) {
        uint32_t base = sbase + (uint32_t)sel * 30720u;
#pragma unroll
        for (int it = 0; it < 2; it++) {
            int c   = tid + it * 256;          // 0..511
            int row = c >> 2;                  // 0..127
            int sub = (c & 3) * 8;             // fp16 offset 0,8,16,24
            uint32_t so = (uint32_t)(row * 80 + sub * 2);
            cpa16(base + so,           A   + (size_t)(bm + row) * K + kt + sub);
            cpa16(base + 10240u + so,  Bhp + (size_t)(bn + row) * K + kt + sub);
            cpa16(base + 20480u + so,  Blp + (size_t)(bn + row) * K + kt + sub);
        }
        CP_COMMIT;
    };

    issue(0, 0);

    const int nstages = K >> 5;   // 32
    for (int it = 0; it < nstages; it++) {
        const int cur = it & 1;
        if (it < nstages - 1) issue((it + 1) * 32, cur ^ 1);
        if (it < nstages - 1) { CP_WAIT1; } else { CP_WAIT0; }
        __syncthreads();

        uint32_t abase = sbase + (uint32_t)cur * 30720u;
#pragma unroll
        for (int ks = 0; ks < 2; ks++) {
            uint32_t koff = (uint32_t)(ks * 32);
            uint32_t a[4][4], bh[2][4], bl[2][4];
#pragma unroll
            for (int mt = 0; mt < 4; mt++)
                ldsm4(abase + (uint32_t)((wm + mt * 16) * 80) + lanoffA + koff,
                      a[mt][0], a[mt][1], a[mt][2], a[mt][3]);
#pragma unroll
            for (int g = 0; g < 2; g++) {
                uint32_t ro = (uint32_t)((wn + g * 16) * 80) + lanoffB + koff;
                ldsm4(abase + 10240u + ro, bh[g][0], bh[g][1], bh[g][2], bh[g][3]);
                ldsm4(abase + 20480u + ro, bl[g][0], bl[g][1], bl[g][2], bl[g][3]);
            }
#pragma unroll
            for (int mt = 0; mt < 4; mt++)
#pragma unroll
                for (int g = 0; g < 2; g++) {
                    mma16816h(acc[mt][2*g],   a[mt][0], a[mt][1], a[mt][2], a[mt][3], bh[g][0], bh[g][1]);
                    mma16816h(acc[mt][2*g],   a[mt][0], a[mt][1], a[mt][2], a[mt][3], bl[g][0], bl[g][1]);
                    mma16816h(acc[mt][2*g+1], a[mt][0], a[mt][1], a[mt][2], a[mt][3], bh[g][2], bh[g][3]);
                    mma16816h(acc[mt][2*g+1], a[mt][0], a[mt][1], a[mt][2], a[mt][3], bl[g][2], bl[g][3]);
                }
        }
        __syncthreads();
    }

#pragma unroll
    for (int mt = 0; mt < 4; mt++) {
#pragma unroll
        for (int nt = 0; nt < 4; nt++) {
            int r0 = bm + wm + mt * 16 + gid;
            int c0 = bn + wn + nt * 8 + tig * 2;
            float2 v01 = make_float2(acc[mt][nt][0] * alpha, acc[mt][nt][1] * alpha);
            float2 v23 = make_float2(acc[mt][nt][2] * alpha, acc[mt][nt][3] * alpha);
            *reinterpret_cast<float2*>(C + (size_t)r0 * N + c0)       = v01;
            *reinterpret_cast<float2*>(C + (size_t)(r0 + 8) * N + c0) = v23;
        }
    }
}

// ---------------- RoPE on Q (in place), fp32 math ----------------
__global__ __launch_bounds__(256) void rope_q_kernel()
{
    int idx = blockIdx.x * blockDim.x + threadIdx.x;
    int i    = idx & 31;
    int head = (idx >> 5) & (NHH - 1);
    int row  = idx >> 9;
    int t    = row & (TT - 1);
    float* p = g_Q + (size_t)row * HHC + head * HDD + i;
    float x1 = p[0], x2 = p[32];
    float invf = exp2f(NLOG2F_STEP * (float)i);
    float arg = (float)t * invf;
    float s, c; sincosf(arg, &s, &c);
    p[0]  = x1 * c - x2 * s;
    p[32] = x2 * c + x1 * s;
}

// ---------------- Gather K + RoPE, write fp16 [B,S,H] ----------------
__global__ __launch_bounds__(256) void gather_k_kernel(const int* __restrict__ outcell)
{
    int idx = blockIdx.x * blockDim.x + threadIdx.x;
    int i    = idx & 31;
    int head = (idx >> 5) & (NHH - 1);
    int rest = idx >> 9;
    int s    = rest % SSQ;
    int b    = rest / SSQ;
    int src  = (s < TT) ? s : outcell[b * EE + (s - TT)];

    size_t soff = (size_t)(b * TT + src) * HHC + head * HDD + i;
    size_t doff = (size_t)(b * SSQ + s) * HHC + head * HDD + i;

    float k1 = g_K[soff], k2 = g_K[soff + 32];
    float invf = exp2f(NLOG2F_STEP * (float)i);
    float arg = (float)s * invf;
    float sn, cs; sincosf(arg, &sn, &cs);
    g_Kh[doff]      = __float2half_rn(k1 * cs - k2 * sn);
    g_Kh[doff + 32] = __float2half_rn(k2 * cs + k1 * sn);
}

// ---------------- Gather V transposed via smem (coalesced both sides) ----------------
__global__ __launch_bounds__(256) void gather_vt_kernel(const int* __restrict__ outcell)
{
    __shared__ float ts[64][65];
    const int tid = threadIdx.x;
    const int s0  = blockIdx.x * 64;
    const int bh  = blockIdx.y;
    const int b   = bh >> 4, h = bh & (NHH - 1);

#pragma unroll
    for (int it = 0; it < 16; it++) {
        int sl = it * 4 + (tid >> 6);
        int d  = tid & 63;
        int s  = s0 + sl;
        int src = (s < TT) ? s : outcell[b * EE + (s - TT)];
        ts[d][sl] = g_V[(size_t)(b * TT + src) * HHC + h * HDD + d];
    }
    __syncthreads();

    int d  = tid >> 2;
    int sq = (tid & 3) * 16;
    uint32_t ph[8];
#pragma unroll
    for (int j = 0; j < 8; j++) {
        __half2 t = __floats2half2_rn(ts[d][sq + 2*j], ts[d][sq + 2*j + 1]);
        ph[j] = *(uint32_t*)&t;
    }
    size_t o = (size_t)(bh * HDD + d) * SSQ + s0 + sq;
    *(uint4*)(g_Vth + o)     = make_uint4(ph[0], ph[1], ph[2], ph[3]);
    *(uint4*)(g_Vth + o + 8) = make_uint4(ph[4], ph[5], ph[6], ph[7]);
}

// ---------------- Attention: flash, pure fp16 mma (fp32 accum), cp.async DB ----------------
#define ATT_SMEM 55552
__global__ __launch_bounds__(256, 2) void attn_mma_kernel(
    const float* __restrict__ bias, const float* __restrict__ lw,
    const unsigned char* __restrict__ keypad, const unsigned char* __restrict__ expand)
{
    extern __shared__ char smraw[];
    __half* Qh = (__half*)smraw;
    float* maskS = (float*)(smraw + 55296);
    const uint32_t sbase = (uint32_t)__cvta_generic_to_shared(smraw);

    const int tid  = threadIdx.x;
    const int lane = tid & 31;
    const int w    = tid >> 5;
    const int gid  = lane >> 2;
    const int tig  = lane & 3;
    const int h = blockIdx.y, b = blockIdx.z;
    const int bh = b * NHH + h;
    const int q0 = blockIdx.x * 128;
    const int qw = w * 16;

    const __half* gKh  = g_Kh  + (size_t)b * SSQ * HHC + h * HDD;
    const __half* gVth = g_Vth + (size_t)bh * HDD * SSQ;

    auto issue_tile = [&](int kc, int sel) {
        uint32_t bbase = sbase + 18432u + (uint32_t)sel * 18432u;
#pragma unroll
        for (int half_ = 0; half_ < 2; half_++) {
            int chunk = tid + half_ * 256;
            int row = chunk >> 3;
            int ce  = (chunk & 7) * 8;
            uint32_t so = (uint32_t)(row * 72 + ce) * 2;
            cpa16(bbase + so,         gKh  + (size_t)(kc + row) * HHC + ce);
            cpa16(bbase + 9216u + so, gVth + (size_t)row * SSQ + kc + ce);
        }
        CP_COMMIT;
    };

    issue_tile(0, 0);

    // ---- stage Q (fp16) ----
#pragma unroll
    for (int it = 0; it < 8; it++) {
        int f4 = tid + it * 256;
        int r  = f4 >> 4;
        int c  = (f4 & 15) * 4;
        float4 v = *(const float4*)(g_Q + (size_t)(b * TT + q0 + r) * HHC + h * HDD + c);
        Qh[r*72+c+0] = __float2half_rn(v.x);
        Qh[r*72+c+1] = __float2half_rn(v.y);
        Qh[r*72+c+2] = __float2half_rn(v.z);
        Qh[r*72+c+3] = __float2half_rn(v.w);
    }
    __syncthreads();

    // ---- Q fragments (resident) ----
    uint32_t qh[4][4];
#pragma unroll
    for (int ks = 0; ks < 4; ks++) {
        int c0 = 2 * tig + 16 * ks;
        qh[ks][0] = *(uint32_t*)&Qh[(qw + gid)     * 72 + c0];
        qh[ks][1] = *(uint32_t*)&Qh[(qw + gid + 8) * 72 + c0];
        qh[ks][2] = *(uint32_t*)&Qh[(qw + gid)     * 72 + c0 + 8];
        qh[ks][3] = *(uint32_t*)&Qh[(qw + gid + 8) * 72 + c0 + 8];
    }

    float m0 = -INFINITY, m1 = -INFINITY, l0 = 0.f, l1 = 0.f;
    float pacc[8][4];
#pragma unroll
    for (int nt = 0; nt < 8; nt++)
#pragma unroll
        for (int c = 0; c < 4; c++) pacc[nt][c] = 0.f;

    const float* biasB = bias + ((size_t)(b * NHH + h) * TT + q0) * SSQ;
    const float* lwB   = lw   + ((size_t)b * TT + q0) * SSQ;

    const uint32_t lanoff =
        (uint32_t)((((lane >> 4) & 1) * 8 + (lane & 7)) * 72 + ((lane >> 3) & 1) * 8) * 2;

    for (int i = 0; i < 24; i++) {
        const int kc = i * 64;
        const int cur = i & 1;
        if (i < 23) issue_tile(kc + 64, cur ^ 1);
        if (i < 23) { CP_WAIT1; } else { CP_WAIT0; }
        if (tid < 64) {
            int s = kc + tid;
            unsigned char mk = (s < TT) ? keypad[b * TT + s] : expand[b * EE + (s - TT)];
            maskS[tid] = mk ? 1.f : 0.f;
        }
        __syncthreads();

        const uint32_t kb = sbase + 18432u + (uint32_t)cur * 18432u;
        const uint32_t vb = kb + 9216u;

        // ---- QK^T (single-pass fp16) ----
        float sacc[8][4];
#pragma unroll
        for (int nt = 0; nt < 8; nt++)
#pragma unroll
            for (int c = 0; c < 4; c++) sacc[nt][c] = 0.f;

#pragma unroll
        for (int ks = 0; ks < 4; ks++) {
#pragma unroll
            for (int p = 0; p < 4; p++) {
                uint32_t off = lanoff + (uint32_t)(p * 2304 + ks * 32);
                uint32_t bh0, bh1, bh2, bh3;
                ldsm4(kb + off, bh0, bh1, bh2, bh3);
                mma16816h(sacc[2*p],   qh[ks][0], qh[ks][1], qh[ks][2], qh[ks][3], bh0, bh1);
                mma16816h(sacc[2*p+1], qh[ks][0], qh[ks][1], qh[ks][2], qh[ks][3], bh2, bh3);
            }
        }

        // ---- pass 1: + bias, masks, row max; cache lw as half2 regs ----
        __half2 lwc0[8], lwc1[8];
        float rmax0 = -INFINITY, rmax1 = -INFINITY;
#pragma unroll
        for (int nt = 0; nt < 8; nt++) {
            int col = kc + 8 * nt + 2 * tig;
            float2 bb0 = __ldg((const float2*)(biasB + (size_t)(qw + gid)     * SSQ + col));
            float2 bb1 = __ldg((const float2*)(biasB + (size_t)(qw + gid + 8) * SSQ + col));
            float2 w0  = __ldg((const float2*)(lwB   + (size_t)(qw + gid)     * SSQ + col));
            float2 w1  = __ldg((const float2*)(lwB   + (size_t)(qw + gid + 8) * SSQ + col));
            lwc0[nt] = __floats2half2_rn(w0.x, w0.y);
            lwc1[nt] = __floats2half2_rn(w1.x, w1.y);
            float mk0 = maskS[8 * nt + 2 * tig];
            float mk1 = maskS[8 * nt + 2 * tig + 1];
            float v0 = sacc[nt][0] + bb0.x; if (mk0 != 0.f || w0.x <= 1e-5f) v0 = -INFINITY;
            float v1 = sacc[nt][1] + bb0.y; if (mk1 != 0.f || w0.y <= 1e-5f) v1 = -INFINITY;
            float v2 = sacc[nt][2] + bb1.x; if (mk0 != 0.f || w1.x <= 1e-5f) v2 = -INFINITY;
            float v3 = sacc[nt][3] + bb1.y; if (mk1 != 0.f || w1.y <= 1e-5f) v3 = -INFINITY;
            sacc[nt][0] = v0; sacc[nt][1] = v1; sacc[nt][2] = v2; sacc[nt][3] = v3;
            rmax0 = fmaxf(rmax0, fmaxf(v0, v1));
            rmax1 = fmaxf(rmax1, fmaxf(v2, v3));
        }
        rmax0 = fmaxf(rmax0, __shfl_xor_sync(0xffffffffu, rmax0, 1));
        rmax0 = fmaxf(rmax0, __shfl_xor_sync(0xffffffffu, rmax0, 2));
        rmax1 = fmaxf(rmax1, __shfl_xor_sync(0xffffffffu, rmax1, 1));
        rmax1 = fmaxf(rmax1, __shfl_xor_sync(0xffffffffu, rmax1, 2));

        float mn0 = fmaxf(m0, rmax0), mn1 = fmaxf(m1, rmax1);
        float sc0 = (mn0 == -INFINITY) ? 1.f : __expf(m0 - mn0);
        float sc1 = (mn1 == -INFINITY) ? 1.f : __expf(m1 - mn1);
        m0 = mn0; m1 = mn1;

#pragma unroll
        for (int nt = 0; nt < 8; nt++) {
            pacc[nt][0] *= sc0; pacc[nt][1] *= sc0;
            pacc[nt][2] *= sc1; pacc[nt][3] *= sc1;
        }

        // ---- fused pass 2 + PV (single-pass fp16, lw from regs) ----
        float ps0 = 0.f, ps1 = 0.f;
#pragma unroll
        for (int ks = 0; ks < 4; ks++) {
            uint32_t ah[4];
#pragma unroll
            for (int j = 0; j < 2; j++) {
                int nt = 2 * ks + j;
                float e0 = (sacc[nt][0] == -INFINITY) ? 0.f : __expf(sacc[nt][0] - mn0);
                float e1 = (sacc[nt][1] == -INFINITY) ? 0.f : __expf(sacc[nt][1] - mn0);
                float e2 = (sacc[nt][2] == -INFINITY) ? 0.f : __expf(sacc[nt][2] - mn1);
                float e3 = (sacc[nt][3] == -INFINITY) ? 0.f : __expf(sacc[nt][3] - mn1);
                ps0 += e0 + e1; ps1 += e2 + e3;
                __half2 t0 = __hmul2(__floats2half2_rn(e0, e1), lwc0[nt]);
                __half2 t1 = __hmul2(__floats2half2_rn(e2, e3), lwc1[nt]);
                ah[2*j]     = *(uint32_t*)&t0;
                ah[2*j + 1] = *(uint32_t*)&t1;
            }
#pragma unroll
            for (int p = 0; p < 4; p++) {
                uint32_t off = lanoff + (uint32_t)(p * 2304 + ks * 32);
                uint32_t vh0, vh1, vh2, vh3;
                ldsm4(vb + off, vh0, vh1, vh2, vh3);
                mma16816h(pacc[2*p],   ah[0], ah[1], ah[2], ah[3], vh0, vh1);
                mma16816h(pacc[2*p+1], ah[0], ah[1], ah[2], ah[3], vh2, vh3);
            }
        }
        ps0 += __shfl_xor_sync(0xffffffffu, ps0, 1);
        ps0 += __shfl_xor_sync(0xffffffffu, ps0, 2);
        ps1 += __shfl_xor_sync(0xffffffffu, ps1, 1);
        ps1 += __shfl_xor_sync(0xffffffffu, ps1, 2);
        l0 = l0 * sc0 + ps0;
        l1 = l1 * sc1 + ps1;
        __syncthreads();
    }

    // ---- epilogue ----
    float inv0 = 1.f / l0, inv1 = 1.f / l1;
#pragma unroll
    for (int nt = 0; nt < 8; nt++) {
        int d = 8 * nt + 2 * tig;
        size_t o0 = (size_t)(b * TT + q0 + qw + gid)     * HHC + h * HDD + d;
        size_t o1 = (size_t)(b * TT + q0 + qw + gid + 8) * HHC + h * HDD + d;
        *(float2*)(g_att + o0) = make_float2(pacc[nt][0] * inv0, pacc[nt][1] * inv0);
        *(float2*)(g_att + o1) = make_float2(pacc[nt][2] * inv1, pacc[nt][3] * inv1);
    }
}

// ---------------- LayerNorm over H=1024, emit fp16 ----------------
__global__ __launch_bounds__(256) void ln_kernel(
    const float* __restrict__ gam, const float* __restrict__ bet)
{
    __shared__ float red[2][32];
    int row = blockIdx.x;
    const float* x = g_att + (size_t)row * HHC;
    float v[4], s = 0.f, sq = 0.f;
#pragma unroll
    for (int i = 0; i < 4; i++) {
        v[i] = x[threadIdx.x + i * 256];
        s += v[i]; sq += v[i] * v[i];
    }
#pragma unroll
    for (int o = 16; o; o >>= 1) {
        s  += __shfl_xor_sync(0xffffffffu, s,  o);
        sq += __shfl_xor_sync(0xffffffffu, sq, o);
    }
    int lane = threadIdx.x & 31, w = threadIdx.x >> 5;
    if (lane == 0) { red[0][w] = s; red[1][w] = sq; }
    __syncthreads();
    if (w == 0) {
        s  = (lane < 8) ? red[0][lane] : 0.f;
        sq = (lane < 8) ? red[1][lane] : 0.f;
#pragma unroll
        for (int o = 4; o; o >>= 1) {
            s  += __shfl_xor_sync(0xffffffffu, s,  o);
            sq += __shfl_xor_sync(0xffffffffu, sq, o);
        }
        if (lane == 0) { red[0][0] = s; red[1][0] = sq; }
    }
    __syncthreads();
    float mu  = red[0][0] * (1.f / HHC);
    float var = red[1][0] * (1.f / HHC) - mu * mu;
    float rs  = rsqrtf(var + LN_EPS);
#pragma unroll
    for (int i = 0; i < 4; i++) {
        int c = threadIdx.x + i * 256;
        g_LNh[(size_t)row * HHC + c] = __float2half_rn((v[i] - mu) * rs * gam[c] + bet[c]);
    }
}

// ---------------- launch ----------------
extern "C" void kernel_launch(void* const* d_in, const int* in_sizes, int n_in,
                              void* d_out, int out_size)
{
    const float* x    = (const float*)d_in[0];
    const float* bias = (const float*)d_in[1];
    const float* lw   = (const float*)d_in[2];
    const unsigned char* kpm = (const unsigned char*)d_in[3];
    const int*   outcell = (const int*)d_in[4];
    const unsigned char* epm = (const unsigned char*)d_in[5];
    const float* wq  = (const float*)d_in[6];
    const float* wk  = (const float*)d_in[7];
    const float* wv  = (const float*)d_in[8];
    const float* wo  = (const float*)d_in[9];
    const float* lng = (const float*)d_in[10];
    const float* lnb = (const float*)d_in[11];
    float* out = (float*)d_out;

    float *Q, *K, *V;
    __half *Xh, *LNh, *Wh, *Wl;
    cudaGetSymbolAddress((void**)&Q,   g_Q);
    cudaGetSymbolAddress((void**)&K,   g_K);
    cudaGetSymbolAddress((void**)&V,   g_V);
    cudaGetSymbolAddress((void**)&Xh,  g_Xh);
    cudaGetSymbolAddress((void**)&LNh, g_LNh);
    cudaGetSymbolAddress((void**)&Wh,  g_Wh);
    cudaGetSymbolAddress((void**)&Wl,  g_Wl);

    cudaFuncSetAttribute(gemm_fp16_nt, cudaFuncAttributeMaxDynamicSharedMemorySize, GEMM_SMEM);
    cudaFuncSetAttribute(attn_mma_kernel, cudaFuncAttributeMaxDynamicSharedMemorySize, ATT_SMEM);

    split_w_kernel<<<(4 * HHC * HHC) / 256, 256>>>(wq, wk, wv, wo);
    xh_kernel<<<(BB * TT * HHC) / 1024, 256>>>(x);

    const int WSZ = HHC * HHC;
    dim3 gg(HHC / 128, (BB * TT) / 128);
    gemm_fp16_nt<<<gg, 256, GEMM_SMEM>>>(Xh, Wh,         Wl,         Q, BB * TT, HHC, HHC, SCALING);
    gemm_fp16_nt<<<gg, 256, GEMM_SMEM>>>(Xh, Wh + WSZ,   Wl + WSZ,   K, BB * TT, HHC, HHC, 1.f);
    gemm_fp16_nt<<<gg, 256, GEMM_SMEM>>>(Xh, Wh + 2*WSZ, Wl + 2*WSZ, V, BB * TT, HHC, HHC, 1.f);

    rope_q_kernel<<<(BB * TT * NHH * 32) / 256, 256>>>();
    gather_k_kernel<<<(BB * SSQ * NHH * 32) / 256, 256>>>(outcell);
    gather_vt_kernel<<<dim3(SSQ / 64, BB * NHH), 256>>>(outcell);

    attn_mma_kernel<<<dim3(TT / 128, NHH, BB), 256, ATT_SMEM>>>(bias, lw, kpm, epm);

    ln_kernel<<<BB * TT, 256>>>(lng, lnb);

    gemm_fp16_nt<<<gg, 256, GEMM_SMEM>>>(LNh, Wh + 3*WSZ, Wl + 3*WSZ, out, BB * TT, HHC, HHC, 1.f);
}

// round 17
// speedup vs baseline: 2.3470x; 1.2570x over previous
#include <cuda_runtime.h>
#include <cuda_fp16.h>
#include <cstdint>

// Problem constants
#define BB   4
#define TT   1024
#define EE   512
#define SSQ  1536   // S = T + E
#define HHC  1024   // hidden
#define NHH  16
#define HDD  64
#define LN_EPS 1e-5f
#define SCALING 0.125f   // sqrt(64)/64

// -log2(10000)/32
#define NLOG2F_STEP (-0.4152410118609203f)

// ---------------- scratch ----------------
__device__ float g_Q  [BB*TT*HHC];    // rope'd Q, [B,T,H]
__device__ float g_K  [BB*TT*HHC];    // raw K projection
__device__ float g_V  [BB*TT*HHC];    // raw V projection
__device__ float g_att[BB*TT*HHC];    // attention out pre-LN
// fp16 staging
__device__ __half g_Xh [BB*TT*HHC];      // fp16(x)
__device__ __half g_LNh[BB*TT*HHC];      // fp16(LN out)
__device__ __half g_Wh [4*HHC*HHC];      // fp16 weights (q,k,v,o)
// fp16 K (gathered+rope'd), [B,S,H]
__device__ __half g_Kh[BB*SSQ*HHC];
// fp16 V, transposed per head: [B*NH, HD, S]
__device__ __half g_Vth[BB*NHH*HDD*SSQ];

// ---------------- helpers ----------------
__device__ __forceinline__ void mma16816h(float* c,
    uint32_t a0, uint32_t a1, uint32_t a2, uint32_t a3,
    uint32_t b0, uint32_t b1)
{
    asm volatile(
        "mma.sync.aligned.m16n8k16.row.col.f32.f16.f16.f32 "
        "{%0,%1,%2,%3},{%4,%5,%6,%7},{%8,%9},{%0,%1,%2,%3};"
        : "+f"(c[0]), "+f"(c[1]), "+f"(c[2]), "+f"(c[3])
        : "r"(a0), "r"(a1), "r"(a2), "r"(a3), "r"(b0), "r"(b1));
}

__device__ __forceinline__ void ldsm4(uint32_t addr,
    uint32_t& r0, uint32_t& r1, uint32_t& r2, uint32_t& r3)
{
    asm volatile("ldmatrix.sync.aligned.m8n8.x4.shared.b16 {%0,%1,%2,%3}, [%4];"
        : "=r"(r0), "=r"(r1), "=r"(r2), "=r"(r3) : "r"(addr));
}

__device__ __forceinline__ void cpa16(uint32_t daddr, const void* src) {
    asm volatile("cp.async.cg.shared.global [%0], [%1], 16;" :: "r"(daddr), "l"(src));
}
#define CP_COMMIT asm volatile("cp.async.commit_group;")
#define CP_WAIT2  asm volatile("cp.async.wait_group 2;")
#define CP_WAIT1  asm volatile("cp.async.wait_group 1;")
#define CP_WAIT0  asm volatile("cp.async.wait_group 0;")

// ---------------- prologue: weights + x -> fp16 (fused, float4-granular) ----------------
// idx < 1M: weights (4 matrices x 256K float4), else x (1M float4)
__global__ __launch_bounds__(256) void prep_kernel(
    const float* __restrict__ x,
    const float* __restrict__ w0, const float* __restrict__ w1,
    const float* __restrict__ w2, const float* __restrict__ w3)
{
    int idx = blockIdx.x * 256 + threadIdx.x;   // 0 .. 2M-1 float4 units
    const int WQ4 = (HHC * HHC) / 4;            // 256K float4 per matrix
    if (idx < 4 * WQ4) {
        int m = idx >> 18;                      // 2^18 = 256K
        const float* src = (m == 0) ? w0 : (m == 1) ? w1 : (m == 2) ? w2 : w3;
        float4 v = *(const float4*)(src + (size_t)(idx & (WQ4 - 1)) * 4);
        __half2 a = __floats2half2_rn(v.x, v.y);
        __half2 b = __floats2half2_rn(v.z, v.w);
        *(uint2*)(g_Wh + (size_t)idx * 4) = make_uint2(*(uint32_t*)&a, *(uint32_t*)&b);
    } else {
        int j = idx - 4 * WQ4;                  // 0 .. 1M-1
        float4 v = *(const float4*)(x + (size_t)j * 4);
        __half2 a = __floats2half2_rn(v.x, v.y);
        __half2 b = __floats2half2_rn(v.z, v.w);
        *(uint2*)(g_Xh + (size_t)j * 4) = make_uint2(*(uint32_t*)&a, *(uint32_t*)&b);
    }
}

// ---------------- GEMM: C[M,N] = alpha * A[M,K] * W[N,K]^T (pure fp16, fp32 accum) ----------------
// 3-stage cp.async ring; stage = A[128][40] (10240 B) + B[128][40] (10240 B).
// blockIdx.z selects weight matrix (wbase+z) and output pointer.
#define GEMM_SMEM 61440
__global__ __launch_bounds__(256, 2) void gemm_fp16_nt(
    const __half* __restrict__ A, int wbase,
    float* __restrict__ C0, float* __restrict__ C1, float* __restrict__ C2)
{
    extern __shared__ char gsm[];
    const uint32_t sbase = (uint32_t)__cvta_generic_to_shared(gsm);

    const int z = blockIdx.z;
    const __half* W = g_Wh + (size_t)(wbase + z) * HHC * HHC;
    float* C = (z == 0) ? C0 : (z == 1) ? C1 : C2;
    const float alpha = (wbase + z == 0) ? SCALING : 1.f;
    const int K = HHC, N = HHC;

    const int tid  = threadIdx.x;
    const int lane = tid & 31;
    const int wid  = tid >> 5;
    const int gid  = lane >> 2;
    const int tig  = lane & 3;
    const int wm   = (wid & 1) * 64;
    const int wn   = (wid >> 1) * 32;
    const int bm   = blockIdx.y * 128;
    const int bn   = blockIdx.x * 128;

    const uint32_t lanoffA =
        (uint32_t)((lane & 15) * 80 + (lane >> 4) * 16);
    const uint32_t lanoffB =
        (uint32_t)((((lane >> 4) & 1) * 8 + (lane & 7)) * 80 + ((lane >> 3) & 1) * 16);

    float acc[4][4][4];
#pragma unroll
    for (int i = 0; i < 4; i++)
#pragma unroll
        for (int j = 0; j < 4; j++)
#pragma unroll
            for (int r = 0; r < 4; r++) acc[i][j][r] = 0.f;

    auto issue = [&](int kt, int sel) {
        uint32_t base = sbase + (uint32_t)sel * 20480u;
#pragma unroll
        for (int it = 0; it < 2; it++) {
            int c   = tid + it * 256;          // 0..511
            int row = c >> 2;                  // 0..127
            int sub = (c & 3) * 8;             // fp16 offset 0,8,16,24
            uint32_t so = (uint32_t)(row * 80 + sub * 2);
            cpa16(base + so,          A + (size_t)(bm + row) * K + kt + sub);
            cpa16(base + 10240u + so, W + (size_t)(bn + row) * K + kt + sub);
        }
        CP_COMMIT;
    };

    issue(0, 0);
    issue(32, 1);

    for (int it = 0; it < 32; it++) {
        const int cur = it % 3;
        if (it + 2 < 32) issue((it + 2) * 32, (it + 2) % 3);
        if (it < 30) { CP_WAIT2; } else if (it == 30) { CP_WAIT1; } else { CP_WAIT0; }
        __syncthreads();

        uint32_t abase = sbase + (uint32_t)cur * 20480u;
#pragma unroll
        for (int ks = 0; ks < 2; ks++) {
            uint32_t koff = (uint32_t)(ks * 32);
            uint32_t a[4][4], bf[2][4];
#pragma unroll
            for (int mt = 0; mt < 4; mt++)
                ldsm4(abase + (uint32_t)((wm + mt * 16) * 80) + lanoffA + koff,
                      a[mt][0], a[mt][1], a[mt][2], a[mt][3]);
#pragma unroll
            for (int g = 0; g < 2; g++)
                ldsm4(abase + 10240u + (uint32_t)((wn + g * 16) * 80) + lanoffB + koff,
                      bf[g][0], bf[g][1], bf[g][2], bf[g][3]);
#pragma unroll
            for (int mt = 0; mt < 4; mt++)
#pragma unroll
                for (int g = 0; g < 2; g++) {
                    mma16816h(acc[mt][2*g],   a[mt][0], a[mt][1], a[mt][2], a[mt][3], bf[g][0], bf[g][1]);
                    mma16816h(acc[mt][2*g+1], a[mt][0], a[mt][1], a[mt][2], a[mt][3], bf[g][2], bf[g][3]);
                }
        }
        __syncthreads();
    }

#pragma unroll
    for (int mt = 0; mt < 4; mt++) {
#pragma unroll
        for (int nt = 0; nt < 4; nt++) {
            int r0 = bm + wm + mt * 16 + gid;
            int c0 = bn + wn + nt * 8 + tig * 2;
            float2 v01 = make_float2(acc[mt][nt][0] * alpha, acc[mt][nt][1] * alpha);
            float2 v23 = make_float2(acc[mt][nt][2] * alpha, acc[mt][nt][3] * alpha);
            *reinterpret_cast<float2*>(C + (size_t)r0 * N + c0)       = v01;
            *reinterpret_cast<float2*>(C + (size_t)(r0 + 8) * N + c0) = v23;
        }
    }
}

// ---------------- RoPE on Q (in place), fp32 math ----------------
__global__ __launch_bounds__(256) void rope_q_kernel()
{
    int idx = blockIdx.x * blockDim.x + threadIdx.x;
    int i    = idx & 31;
    int head = (idx >> 5) & (NHH - 1);
    int row  = idx >> 9;
    int t    = row & (TT - 1);
    float* p = g_Q + (size_t)row * HHC + head * HDD + i;
    float x1 = p[0], x2 = p[32];
    float invf = exp2f(NLOG2F_STEP * (float)i);
    float arg = (float)t * invf;
    float s, c; sincosf(arg, &s, &c);
    p[0]  = x1 * c - x2 * s;
    p[32] = x2 * c + x1 * s;
}

// ---------------- Gather K + RoPE, write fp16 [B,S,H] ----------------
__global__ __launch_bounds__(256) void gather_k_kernel(const int* __restrict__ outcell)
{
    int idx = blockIdx.x * blockDim.x + threadIdx.x;
    int i    = idx & 31;
    int head = (idx >> 5) & (NHH - 1);
    int rest = idx >> 9;
    int s    = rest % SSQ;
    int b    = rest / SSQ;
    int src  = (s < TT) ? s : outcell[b * EE + (s - TT)];

    size_t soff = (size_t)(b * TT + src) * HHC + head * HDD + i;
    size_t doff = (size_t)(b * SSQ + s) * HHC + head * HDD + i;

    float k1 = g_K[soff], k2 = g_K[soff + 32];
    float invf = exp2f(NLOG2F_STEP * (float)i);
    float arg = (float)s * invf;
    float sn, cs; sincosf(arg, &sn, &cs);
    g_Kh[doff]      = __float2half_rn(k1 * cs - k2 * sn);
    g_Kh[doff + 32] = __float2half_rn(k2 * cs + k1 * sn);
}

// ---------------- Gather V transposed via smem (coalesced both sides) ----------------
__global__ __launch_bounds__(256) void gather_vt_kernel(const int* __restrict__ outcell)
{
    __shared__ float ts[64][65];
    const int tid = threadIdx.x;
    const int s0  = blockIdx.x * 64;
    const int bh  = blockIdx.y;
    const int b   = bh >> 4, h = bh & (NHH - 1);

#pragma unroll
    for (int it = 0; it < 16; it++) {
        int sl = it * 4 + (tid >> 6);
        int d  = tid & 63;
        int s  = s0 + sl;
        int src = (s < TT) ? s : outcell[b * EE + (s - TT)];
        ts[d][sl] = g_V[(size_t)(b * TT + src) * HHC + h * HDD + d];
    }
    __syncthreads();

    int d  = tid >> 2;
    int sq = (tid & 3) * 16;
    uint32_t ph[8];
#pragma unroll
    for (int j = 0; j < 8; j++) {
        __half2 t = __floats2half2_rn(ts[d][sq + 2*j], ts[d][sq + 2*j + 1]);
        ph[j] = *(uint32_t*)&t;
    }
    size_t o = (size_t)(bh * HDD + d) * SSQ + s0 + sq;
    *(uint4*)(g_Vth + o)     = make_uint4(ph[0], ph[1], ph[2], ph[3]);
    *(uint4*)(g_Vth + o + 8) = make_uint4(ph[4], ph[5], ph[6], ph[7]);
}

// ---------------- Attention: flash, pure fp16 mma (fp32 accum), cp.async DB ----------------
#define ATT_SMEM 55552
__global__ __launch_bounds__(256, 2) void attn_mma_kernel(
    const float* __restrict__ bias, const float* __restrict__ lw,
    const unsigned char* __restrict__ keypad, const unsigned char* __restrict__ expand)
{
    extern __shared__ char smraw[];
    __half* Qh = (__half*)smraw;
    float* maskS = (float*)(smraw + 55296);
    const uint32_t sbase = (uint32_t)__cvta_generic_to_shared(smraw);

    const int tid  = threadIdx.x;
    const int lane = tid & 31;
    const int w    = tid >> 5;
    const int gid  = lane >> 2;
    const int tig  = lane & 3;
    const int h = blockIdx.y, b = blockIdx.z;
    const int bh = b * NHH + h;
    const int q0 = blockIdx.x * 128;
    const int qw = w * 16;

    const __half* gKh  = g_Kh  + (size_t)b * SSQ * HHC + h * HDD;
    const __half* gVth = g_Vth + (size_t)bh * HDD * SSQ;

    auto issue_tile = [&](int kc, int sel) {
        uint32_t bbase = sbase + 18432u + (uint32_t)sel * 18432u;
#pragma unroll
        for (int half_ = 0; half_ < 2; half_++) {
            int chunk = tid + half_ * 256;
            int row = chunk >> 3;
            int ce  = (chunk & 7) * 8;
            uint32_t so = (uint32_t)(row * 72 + ce) * 2;
            cpa16(bbase + so,         gKh  + (size_t)(kc + row) * HHC + ce);
            cpa16(bbase + 9216u + so, gVth + (size_t)row * SSQ + kc + ce);
        }
        CP_COMMIT;
    };

    issue_tile(0, 0);

    // ---- stage Q (fp16) ----
#pragma unroll
    for (int it = 0; it < 8; it++) {
        int f4 = tid + it * 256;
        int r  = f4 >> 4;
        int c  = (f4 & 15) * 4;
        float4 v = *(const float4*)(g_Q + (size_t)(b * TT + q0 + r) * HHC + h * HDD + c);
        Qh[r*72+c+0] = __float2half_rn(v.x);
        Qh[r*72+c+1] = __float2half_rn(v.y);
        Qh[r*72+c+2] = __float2half_rn(v.z);
        Qh[r*72+c+3] = __float2half_rn(v.w);
    }
    __syncthreads();

    // ---- Q fragments (resident) ----
    uint32_t qh[4][4];
#pragma unroll
    for (int ks = 0; ks < 4; ks++) {
        int c0 = 2 * tig + 16 * ks;
        qh[ks][0] = *(uint32_t*)&Qh[(qw + gid)     * 72 + c0];
        qh[ks][1] = *(uint32_t*)&Qh[(qw + gid + 8) * 72 + c0];
        qh[ks][2] = *(uint32_t*)&Qh[(qw + gid)     * 72 + c0 + 8];
        qh[ks][3] = *(uint32_t*)&Qh[(qw + gid + 8) * 72 + c0 + 8];
    }

    float m0 = -INFINITY, m1 = -INFINITY, l0 = 0.f, l1 = 0.f;
    float pacc[8][4];
#pragma unroll
    for (int nt = 0; nt < 8; nt++)
#pragma unroll
        for (int c = 0; c < 4; c++) pacc[nt][c] = 0.f;

    const float* biasB = bias + ((size_t)(b * NHH + h) * TT + q0) * SSQ;
    const float* lwB   = lw   + ((size_t)b * TT + q0) * SSQ;

    const uint32_t lanoff =
        (uint32_t)((((lane >> 4) & 1) * 8 + (lane & 7)) * 72 + ((lane >> 3) & 1) * 8) * 2;

    for (int i = 0; i < 24; i++) {
        const int kc = i * 64;
        const int cur = i & 1;
        if (i < 23) issue_tile(kc + 64, cur ^ 1);
        if (i < 23) { CP_WAIT1; } else { CP_WAIT0; }
        if (tid < 64) {
            int s = kc + tid;
            unsigned char mk = (s < TT) ? keypad[b * TT + s] : expand[b * EE + (s - TT)];
            maskS[tid] = mk ? 1.f : 0.f;
        }
        __syncthreads();

        const uint32_t kb = sbase + 18432u + (uint32_t)cur * 18432u;
        const uint32_t vb = kb + 9216u;

        // ---- QK^T (single-pass fp16) ----
        float sacc[8][4];
#pragma unroll
        for (int nt = 0; nt < 8; nt++)
#pragma unroll
            for (int c = 0; c < 4; c++) sacc[nt][c] = 0.f;

#pragma unroll
        for (int ks = 0; ks < 4; ks++) {
#pragma unroll
            for (int p = 0; p < 4; p++) {
                uint32_t off = lanoff + (uint32_t)(p * 2304 + ks * 32);
                uint32_t bh0, bh1, bh2, bh3;
                ldsm4(kb + off, bh0, bh1, bh2, bh3);
                mma16816h(sacc[2*p],   qh[ks][0], qh[ks][1], qh[ks][2], qh[ks][3], bh0, bh1);
                mma16816h(sacc[2*p+1], qh[ks][0], qh[ks][1], qh[ks][2], qh[ks][3], bh2, bh3);
            }
        }

        // ---- pass 1: + bias, masks, row max; cache lw as half2 regs ----
        __half2 lwc0[8], lwc1[8];
        float rmax0 = -INFINITY, rmax1 = -INFINITY;
#pragma unroll
        for (int nt = 0; nt < 8; nt++) {
            int col = kc + 8 * nt + 2 * tig;
            float2 bb0 = __ldg((const float2*)(biasB + (size_t)(qw + gid)     * SSQ + col));
            float2 bb1 = __ldg((const float2*)(biasB + (size_t)(qw + gid + 8) * SSQ + col));
            float2 w0  = __ldg((const float2*)(lwB   + (size_t)(qw + gid)     * SSQ + col));
            float2 w1  = __ldg((const float2*)(lwB   + (size_t)(qw + gid + 8) * SSQ + col));
            lwc0[nt] = __floats2half2_rn(w0.x, w0.y);
            lwc1[nt] = __floats2half2_rn(w1.x, w1.y);
            float mk0 = maskS[8 * nt + 2 * tig];
            float mk1 = maskS[8 * nt + 2 * tig + 1];
            float v0 = sacc[nt][0] + bb0.x; if (mk0 != 0.f || w0.x <= 1e-5f) v0 = -INFINITY;
            float v1 = sacc[nt][1] + bb0.y; if (mk1 != 0.f || w0.y <= 1e-5f) v1 = -INFINITY;
            float v2 = sacc[nt][2] + bb1.x; if (mk0 != 0.f || w1.x <= 1e-5f) v2 = -INFINITY;
            float v3 = sacc[nt][3] + bb1.y; if (mk1 != 0.f || w1.y <= 1e-5f) v3 = -INFINITY;
            sacc[nt][0] = v0; sacc[nt][1] = v1; sacc[nt][2] = v2; sacc[nt][3] = v3;
            rmax0 = fmaxf(rmax0, fmaxf(v0, v1));
            rmax1 = fmaxf(rmax1, fmaxf(v2, v3));
        }
        rmax0 = fmaxf(rmax0, __shfl_xor_sync(0xffffffffu, rmax0, 1));
        rmax0 = fmaxf(rmax0, __shfl_xor_sync(0xffffffffu, rmax0, 2));
        rmax1 = fmaxf(rmax1, __shfl_xor_sync(0xffffffffu, rmax1, 1));
        rmax1 = fmaxf(rmax1, __shfl_xor_sync(0xffffffffu, rmax1, 2));

        float mn0 = fmaxf(m0, rmax0), mn1 = fmaxf(m1, rmax1);
        float sc0 = (mn0 == -INFINITY) ? 1.f : __expf(m0 - mn0);
        float sc1 = (mn1 == -INFINITY) ? 1.f : __expf(m1 - mn1);
        m0 = mn0; m1 = mn1;

#pragma unroll
        for (int nt = 0; nt < 8; nt++) {
            pacc[nt][0] *= sc0; pacc[nt][1] *= sc0;
            pacc[nt][2] *= sc1; pacc[nt][3] *= sc1;
        }

        // ---- fused pass 2 + PV (single-pass fp16, lw from regs) ----
        float ps0 = 0.f, ps1 = 0.f;
#pragma unroll
        for (int ks = 0; ks < 4; ks++) {
            uint32_t ah[4];
#pragma unroll
            for (int j = 0; j < 2; j++) {
                int nt = 2 * ks + j;
                float e0 = (sacc[nt][0] == -INFINITY) ? 0.f : __expf(sacc[nt][0] - mn0);
                float e1 = (sacc[nt][1] == -INFINITY) ? 0.f : __expf(sacc[nt][1] - mn0);
                float e2 = (sacc[nt][2] == -INFINITY) ? 0.f : __expf(sacc[nt][2] - mn1);
                float e3 = (sacc[nt][3] == -INFINITY) ? 0.f : __expf(sacc[nt][3] - mn1);
                ps0 += e0 + e1; ps1 += e2 + e3;
                __half2 t0 = __hmul2(__floats2half2_rn(e0, e1), lwc0[nt]);
                __half2 t1 = __hmul2(__floats2half2_rn(e2, e3), lwc1[nt]);
                ah[2*j]     = *(uint32_t*)&t0;
                ah[2*j + 1] = *(uint32_t*)&t1;
            }
#pragma unroll
            for (int p = 0; p < 4; p++) {
                uint32_t off = lanoff + (uint32_t)(p * 2304 + ks * 32);
                uint32_t vh0, vh1, vh2, vh3;
                ldsm4(vb + off, vh0, vh1, vh2, vh3);
                mma16816h(pacc[2*p],   ah[0], ah[1], ah[2], ah[3], vh0, vh1);
                mma16816h(pacc[2*p+1], ah[0], ah[1], ah[2], ah[3], vh2, vh3);
            }
        }
        ps0 += __shfl_xor_sync(0xffffffffu, ps0, 1);
        ps0 += __shfl_xor_sync(0xffffffffu, ps0, 2);
        ps1 += __shfl_xor_sync(0xffffffffu, ps1, 1);
        ps1 += __shfl_xor_sync(0xffffffffu, ps1, 2);
        l0 = l0 * sc0 + ps0;
        l1 = l1 * sc1 + ps1;
        __syncthreads();
    }

    // ---- epilogue ----
    float inv0 = 1.f / l0, inv1 = 1.f / l1;
#pragma unroll
    for (int nt = 0; nt < 8; nt++) {
        int d = 8 * nt + 2 * tig;
        size_t o0 = (size_t)(b * TT + q0 + qw + gid)     * HHC + h * HDD + d;
        size_t o1 = (size_t)(b * TT + q0 + qw + gid + 8) * HHC + h * HDD + d;
        *(float2*)(g_att + o0) = make_float2(pacc[nt][0] * inv0, pacc[nt][1] * inv0);
        *(float2*)(g_att + o1) = make_float2(pacc[nt][2] * inv1, pacc[nt][3] * inv1);
    }
}

// ---------------- LayerNorm over H=1024, emit fp16 ----------------
__global__ __launch_bounds__(256) void ln_kernel(
    const float* __restrict__ gam, const float* __restrict__ bet)
{
    __shared__ float red[2][32];
    int row = blockIdx.x;
    const float* x = g_att + (size_t)row * HHC;
    float v[4], s = 0.f, sq = 0.f;
#pragma unroll
    for (int i = 0; i < 4; i++) {
        v[i] = x[threadIdx.x + i * 256];
        s += v[i]; sq += v[i] * v[i];
    }
#pragma unroll
    for (int o = 16; o; o >>= 1) {
        s  += __shfl_xor_sync(0xffffffffu, s,  o);
        sq += __shfl_xor_sync(0xffffffffu, sq, o);
    }
    int lane = threadIdx.x & 31, w = threadIdx.x >> 5;
    if (lane == 0) { red[0][w] = s; red[1][w] = sq; }
    __syncthreads();
    if (w == 0) {
        s  = (lane < 8) ? red[0][lane] : 0.f;
        sq = (lane < 8) ? red[1][lane] : 0.f;
#pragma unroll
        for (int o = 4; o; o >>= 1) {
            s  += __shfl_xor_sync(0xffffffffu, s,  o);
            sq += __shfl_xor_sync(0xffffffffu, sq, o);
        }
        if (lane == 0) { red[0][0] = s; red[1][0] = sq; }
    }
    __syncthreads();
    float mu  = red[0][0] * (1.f / HHC);
    float var = red[1][0] * (1.f / HHC) - mu * mu;
    float rs  = rsqrtf(var + LN_EPS);
#pragma unroll
    for (int i = 0; i < 4; i++) {
        int c = threadIdx.x + i * 256;
        g_LNh[(size_t)row * HHC + c] = __float2half_rn((v[i] - mu) * rs * gam[c] + bet[c]);
    }
}

// ---------------- launch ----------------
extern "C" void kernel_launch(void* const* d_in, const int* in_sizes, int n_in,
                              void* d_out, int out_size)
{
    const float* x    = (const float*)d_in[0];
    const float* bias = (const float*)d_in[1];
    const float* lw   = (const float*)d_in[2];
    const unsigned char* kpm = (const unsigned char*)d_in[3];
    const int*   outcell = (const int*)d_in[4];
    const unsigned char* epm = (const unsigned char*)d_in[5];
    const float* wq  = (const float*)d_in[6];
    const float* wk  = (const float*)d_in[7];
    const float* wv  = (const float*)d_in[8];
    const float* wo  = (const float*)d_in[9];
    const float* lng = (const float*)d_in[10];
    const float* lnb = (const float*)d_in[11];
    float* out = (float*)d_out;

    float *Q, *K, *V;
    __half *Xh, *LNh;
    cudaGetSymbolAddress((void**)&Q,   g_Q);
    cudaGetSymbolAddress((void**)&K,   g_K);
    cudaGetSymbolAddress((void**)&V,   g_V);
    cudaGetSymbolAddress((void**)&Xh,  g_Xh);
    cudaGetSymbolAddress((void**)&LNh, g_LNh);

    cudaFuncSetAttribute(gemm_fp16_nt, cudaFuncAttributeMaxDynamicSharedMemorySize, GEMM_SMEM);
    cudaFuncSetAttribute(attn_mma_kernel, cudaFuncAttributeMaxDynamicSharedMemorySize, ATT_SMEM);

    // launch 0: fused prologue (weights + x -> fp16)
    prep_kernel<<<8192, 256>>>(x, wq, wk, wv, wo);
    // launch 1: fused Q/K/V projections (gridDim.z = 3)
    gemm_fp16_nt<<<dim3(HHC / 128, (BB * TT) / 128, 3), 256, GEMM_SMEM>>>(Xh, 0, Q, K, V);
    // launches 2-4
    rope_q_kernel<<<(BB * TT * NHH * 32) / 256, 256>>>();
    gather_k_kernel<<<(BB * SSQ * NHH * 32) / 256, 256>>>(outcell);
    gather_vt_kernel<<<dim3(SSQ / 64, BB * NHH), 256>>>(outcell);
    // launch 5: attention  (ncu -s 5 -c 1 captures this)
    attn_mma_kernel<<<dim3(TT / 128, NHH, BB), 256, ATT_SMEM>>>(bias, lw, kpm, epm);
    // launch 6
    ln_kernel<<<BB * TT, 256>>>(lng, lnb);
    // launch 7: output projection
    gemm_fp16_nt<<<dim3(HHC / 128, (BB * TT) / 128, 1), 256, GEMM_SMEM>>>(LNh, 3, out, out, out);
}